// round 7
// baseline (speedup 1.0000x reference)
#include <cuda_runtime.h>
#include <cuda_fp16.h>
#include <math.h>
#include <stdint.h>

// ---------------- problem constants ----------------
#define N0T 123904
#define N1T 11264
#define N2T 1024
#define E0  (N0T*10)
#define E1  (N1T*10)
#define E2  (N2T*10)
#define C_IN 128
#define HID  256
#define OUTC 47
#define BN_EPS 1e-5f

// ---------------- scratch (no allocation allowed) ----------------
__device__ float g_bufA[(size_t)N0T * HID];   // 126.9 MB
__device__ float g_bufB[(size_t)N0T * HID];   // 126.9 MB
__device__ __half g_wHi[7 * 65536];           // transposed weights hi  [N][K]
__device__ __half g_wLo[7 * 65536];           // transposed weights lo
__device__ float g_sum[HID], g_sumsq[HID], g_scale[HID], g_shift[HID];

// ---------------- PTX helpers ----------------
__device__ __forceinline__ uint32_t smem_u32(const void* p) {
    uint32_t a;
    asm("{ .reg .u64 t; cvta.to.shared.u64 t, %1; cvt.u32.u64 %0, t; }" : "=r"(a) : "l"(p));
    return a;
}
__device__ __forceinline__ void ldm_x4(uint32_t* r, uint32_t addr) {
    asm volatile("ldmatrix.sync.aligned.m8n8.x4.shared.b16 {%0,%1,%2,%3}, [%4];"
        : "=r"(r[0]), "=r"(r[1]), "=r"(r[2]), "=r"(r[3]) : "r"(addr));
}
__device__ __forceinline__ void mma16816(float* d, const uint32_t* a, const uint32_t* b) {
    asm volatile("mma.sync.aligned.m16n8k16.row.col.f32.f16.f16.f32 "
        "{%0,%1,%2,%3}, {%4,%5,%6,%7}, {%8,%9}, {%0,%1,%2,%3};"
        : "+f"(d[0]), "+f"(d[1]), "+f"(d[2]), "+f"(d[3])
        : "r"(a[0]), "r"(a[1]), "r"(a[2]), "r"(a[3]), "r"(b[0]), "r"(b[1]));
}
#define CPA16(dst, src) asm volatile("cp.async.cg.shared.global [%0], [%1], 16;" :: "r"(dst), "l"(src))
#define CPA_COMMIT()    asm volatile("cp.async.commit_group;" ::: "memory")
#define CPA_WAIT2()     asm volatile("cp.async.wait_group 2;" ::: "memory")
#define CPA_WAIT1()     asm volatile("cp.async.wait_group 1;" ::: "memory")
#define CPA_WAIT0()     asm volatile("cp.async.wait_group 0;" ::: "memory")

// ---------------- misc kernels ----------------
__global__ void copy_f4(const float* __restrict__ in, float* __restrict__ out, int n4) {
    int i = blockIdx.x * blockDim.x + threadIdx.x;
    int stride = gridDim.x * blockDim.x;
    const float4* in4 = (const float4*)in;
    float4* out4 = (float4*)out;
    for (; i < n4; i += stride) out4[i] = in4[i];
}

template<int C>
__global__ void agg_scatter(const float* __restrict__ x, const int* __restrict__ src,
                            const int* __restrict__ tgt, float* __restrict__ agg, int e) {
    int warp = (blockIdx.x * blockDim.x + threadIdx.x) >> 5;
    int lane = threadIdx.x & 31;
    if (warp >= e) return;
    int s = src[warp];
    int t = tgt[warp];
    const float4* xs = (const float4*)(x + (size_t)s * C);
    float* ao = agg + (size_t)t * C;
#pragma unroll
    for (int i = 0; i < C / 128; i++) {
        int q = lane + i * 32;
        float4 v = xs[q];
        int c = q * 4;
        atomicAdd(ao + c + 0, v.x);
        atomicAdd(ao + c + 1, v.y);
        atomicAdd(ao + c + 2, v.z);
        atomicAdd(ao + c + 3, v.w);
    }
}

__device__ __forceinline__ void split2h(float a, float b, uint32_t& hi, uint32_t& lo) {
    __half2 h = __floats2half2_rn(a, b);
    float2 hf = __half22float2(h);
    __half2 l = __floats2half2_rn(a - hf.x, b - hf.y);
    hi = *reinterpret_cast<uint32_t*>(&h);
    lo = *reinterpret_cast<uint32_t*>(&l);
}

// W[K,N] fp32 -> WT hi/lo [N,K] fp16; optionally zero the BN stat accumulators
__global__ void conv_wT(const float* __restrict__ W, __half* __restrict__ hiT,
                        __half* __restrict__ loT, int K, int N,
                        float* __restrict__ zsum, float* __restrict__ zsumsq) {
    int i = blockIdx.x * blockDim.x + threadIdx.x;
    if (zsum && blockIdx.x == 0 && threadIdx.x < HID) {
        zsum[threadIdx.x] = 0.f;
        zsumsq[threadIdx.x] = 0.f;
    }
    if (i >= K * N) return;
    int k = i / N, n = i % N;
    float v = W[i];
    __half h = __float2half_rn(v);
    float rem = v - __half2float(h);
    hiT[(size_t)n * K + k] = h;
    loT[(size_t)n * K + k] = __float2half_rn(rem);
}

// compute scale/shift from stats, then re-zero stats for the next layer
__global__ void bn_prep(float* __restrict__ sum, float* __restrict__ sumsq,
                        const float* __restrict__ g, const float* __restrict__ be,
                        int M, float* __restrict__ scale, float* __restrict__ shift) {
    int c = threadIdx.x;
    float inv = 1.f / (float)M;
    float mu = sum[c] * inv;
    float var = sumsq[c] * inv - mu * mu;
    float sc = g[c] * rsqrtf(var + BN_EPS);
    scale[c] = sc;
    shift[c] = be[c] - mu * sc;
    sum[c] = 0.f;
    sumsq[c] = 0.f;
}

// ---------------- fused mma.sync GEMM, fp32 A input ----------------
// C[M,256] = op(A)[M,KT] @ W[KT,256] + bias
//   op(A) = BNA ? relu(A*scale[k]+shift[k]) : A
//   output optionally ReLU'd; optionally accumulates column sum/sumsq (for BN).
// A fp32 [M,KT]; W pre-split hi/lo fp16, transposed [256,KT].
// Block tile 128x256x32, 512 threads (16 warps), 3-stage cp.async pipeline.
#define BK 32
#define SPAD 40                          // half-tile row stride (halfs)
#define ATSB (128 * SPAD * 2)            // 10240 B: converted A half tile
#define BTSB (256 * SPAD * 2)            // 20480 B: B half tile per stage
#define AF_STRIDE 36                     // fp32 stage row stride (floats)
#define AF_BYTES (128 * AF_STRIDE * 4)   // 18432 B per fp32 stage
#define S_AF 0                           // 3 stages fp32 A: 55296
#define S_AH (3 * AF_BYTES)              // 55296
#define S_AL (S_AH + ATSB)               // 65536
#define S_BH (S_AL + ATSB)               // 75776  (3 stages: 61440)
#define S_BL (S_BH + 3 * BTSB)           // 137216 (3 stages: 61440)
#define S_SS (S_BL + 3 * BTSB)           // 198656
#define GEMM_SMEM (S_SS + 2048)          // 200704

template<int KT, bool BNA, bool RELUOUT, bool STATS>
__global__ void __launch_bounds__(512, 1) gemm_f32a(
    const float* __restrict__ A, const __half* __restrict__ Bhi, const __half* __restrict__ Blo,
    const float* __restrict__ scale, const float* __restrict__ shift,
    const float* __restrict__ bias, float* __restrict__ C,
    float* __restrict__ gsum, float* __restrict__ gsumsq)
{
    extern __shared__ char smem[];
    const uint32_t sb = smem_u32(smem);
    const int tid = threadIdx.x, wid = tid >> 5, lane = tid & 31;
    const int wrow = wid & 3, wcol = wid >> 2;     // 4 row-warps x 4 col-warps
    constexpr int NC = KT / BK;

    const int brow = blockIdx.x * 128;

    const int lr = tid >> 2;          // 0..127  (A loader/converter row)
    const int lq = tid & 3;           // 0..3    (8-float segment)
    const int br = tid >> 1;          // 0..255  (B loader row)
    const int bsg = tid & 1;          // 0..1    (16-half segment)

    float* scale_s = (float*)(smem + S_SS);
    float* shift_s = scale_s + 256;
    if (BNA && tid < 256) {
        scale_s[tid] = scale[tid];
        shift_s[tid] = shift[tid];
    }

    auto load_stage = [&](int c, int st) {
        // A fp32: 32B per thread
        uint32_t ad = sb + S_AF + st * AF_BYTES + (uint32_t)(lr * AF_STRIDE + lq * 8) * 4;
        const float* pa = A + (size_t)(brow + lr) * KT + c * BK + lq * 8;
        CPA16(ad, pa); CPA16(ad + 16, pa + 4);
        // B hi/lo: 32B each per thread (256 rows)
        uint32_t bdst = (uint32_t)(br * SPAD + bsg * 16) * 2;
        const __half* pb = Bhi + (size_t)br * KT + c * BK + bsg * 16;
        uint32_t bh = sb + S_BH + st * BTSB + bdst;
        CPA16(bh, pb); CPA16(bh + 16, pb + 8);
        const __half* pq = Blo + (size_t)br * KT + c * BK + bsg * 16;
        uint32_t bl = sb + S_BL + st * BTSB + bdst;
        CPA16(bl, pq); CPA16(bl + 16, pq + 8);
        CPA_COMMIT();
    };

    float acc[2][8][4];
#pragma unroll
    for (int i = 0; i < 2; i++)
#pragma unroll
        for (int j = 0; j < 8; j++)
#pragma unroll
            for (int k = 0; k < 4; k++) acc[i][j][k] = 0.f;

    const uint32_t a_row = wrow * 32 + (lane & 15);
    const uint32_t a_coloff = (lane >> 4) * 8;
    const uint32_t b_row_l = (lane & 7) + ((lane >> 4) << 3);
    const uint32_t b_coloff = ((lane >> 3) & 1) * 8;

    load_stage(0, 0);
    if (NC > 1) load_stage(1, 1);

    for (int c = 0; c < NC; c++) {
        int st = c % 3;
        if (c + 2 < NC) {
            load_stage(c + 2, (c + 2) % 3);
            CPA_WAIT2();
        } else if (c + 1 < NC) {
            CPA_WAIT1();
        } else {
            CPA_WAIT0();
        }
        __syncthreads();   // stage c landed; prior iter's mma done (trailing sync)

        // convert fp32 stage -> Ahi/Alo fp16 tiles (8 floats/thread)
        {
            const float* af = (const float*)(smem + S_AF + st * AF_BYTES);
            int base = lr * AF_STRIDE + lq * 8;
            float v[8];
            float4 t0 = *(const float4*)(af + base);
            float4 t1 = *(const float4*)(af + base + 4);
            v[0] = t0.x; v[1] = t0.y; v[2] = t0.z; v[3] = t0.w;
            v[4] = t1.x; v[5] = t1.y; v[6] = t1.z; v[7] = t1.w;
            if (BNA) {
                int k0 = c * BK + lq * 8;
#pragma unroll
                for (int j = 0; j < 8; j++)
                    v[j] = fmaxf(fmaf(v[j], scale_s[k0 + j], shift_s[k0 + j]), 0.f);
            }
            uint32_t h[4], l[4];
#pragma unroll
            for (int i = 0; i < 4; i++) split2h(v[2 * i], v[2 * i + 1], h[i], l[i]);
            char* dh = smem + S_AH + (size_t)(lr * SPAD + lq * 8) * 2;
            char* dl = smem + S_AL + (size_t)(lr * SPAD + lq * 8) * 2;
            *(uint4*)dh = *(uint4*)&h[0];
            *(uint4*)dl = *(uint4*)&l[0];
        }
        __syncthreads();   // conversions visible

        const uint32_t aHiB = sb + S_AH, aLoB = sb + S_AL;
        const uint32_t bHiB = sb + S_BH + st * BTSB;
        const uint32_t bLoB = sb + S_BL + st * BTSB;

#pragma unroll
        for (int ks = 0; ks < 2; ks++) {
            uint32_t ao = (uint32_t)(a_row * SPAD + ks * 16 + a_coloff) * 2;
            uint32_t ah[2][4], al[2][4];
            ldm_x4(ah[0], aHiB + ao);
            ldm_x4(ah[1], aHiB + ao + 16 * SPAD * 2);
            ldm_x4(al[0], aLoB + ao);
            ldm_x4(al[1], aLoB + ao + 16 * SPAD * 2);

#pragma unroll
            for (int nt = 0; nt < 4; nt++) {
                uint32_t bo = (uint32_t)((wcol * 64 + nt * 16 + b_row_l) * SPAD + ks * 16 + b_coloff) * 2;
                uint32_t bh[4], bl[4];
                ldm_x4(bh, bHiB + bo);
                ldm_x4(bl, bLoB + bo);
#pragma unroll
                for (int mf = 0; mf < 2; mf++) {
                    mma16816(acc[mf][nt * 2 + 0], ah[mf], &bh[0]);
                    mma16816(acc[mf][nt * 2 + 0], ah[mf], &bl[0]);
                    mma16816(acc[mf][nt * 2 + 0], al[mf], &bh[0]);
                    mma16816(acc[mf][nt * 2 + 1], ah[mf], &bh[2]);
                    mma16816(acc[mf][nt * 2 + 1], ah[mf], &bl[2]);
                    mma16816(acc[mf][nt * 2 + 1], al[mf], &bh[2]);
                }
            }
        }
        __syncthreads();   // all smem reads done before A-tile overwrite next iter
    }

    // ---------------- epilogue ----------------
    const int row0 = brow + wrow * 32 + (lane >> 2);
    const int col0 = wcol * 64 + (lane & 3) * 2;

    float cs[16], cq[16];
    if (STATS) {
#pragma unroll
        for (int i = 0; i < 16; i++) { cs[i] = 0.f; cq[i] = 0.f; }
    }

#pragma unroll
    for (int mf = 0; mf < 2; mf++) {
#pragma unroll
        for (int nt = 0; nt < 8; nt++) {
            float* d = acc[mf][nt];
            int col = col0 + nt * 8;
            float2 bv = *(const float2*)(bias + col);
            int r0 = row0 + mf * 16;
            float2 v0 = {d[0] + bv.x, d[1] + bv.y};
            float2 v1 = {d[2] + bv.x, d[3] + bv.y};
            if (RELUOUT) {
                v0.x = fmaxf(v0.x, 0.f); v0.y = fmaxf(v0.y, 0.f);
                v1.x = fmaxf(v1.x, 0.f); v1.y = fmaxf(v1.y, 0.f);
            }
            if (STATS) {
                int i0 = nt * 2;
                cs[i0] += v0.x + v1.x;       cq[i0] += v0.x * v0.x + v1.x * v1.x;
                cs[i0 + 1] += v0.y + v1.y;   cq[i0 + 1] += v0.y * v0.y + v1.y * v1.y;
            }
            *(float2*)(C + (size_t)r0 * HID + col) = v0;
            *(float2*)(C + (size_t)(r0 + 8) * HID + col) = v1;
        }
    }

    if (STATS) {
#pragma unroll
        for (int off = 4; off <= 16; off <<= 1) {
#pragma unroll
            for (int i = 0; i < 16; i++) {
                cs[i] += __shfl_xor_sync(0xffffffff, cs[i], off);
                cq[i] += __shfl_xor_sync(0xffffffff, cq[i], off);
            }
        }
        __syncthreads();                       // mainloop smem no longer needed
        float* ssum = (float*)smem;            // [0..255] sum, [256..511] sumsq
        ssum[tid] = 0.f;
        __syncthreads();
        if (lane < 4) {
#pragma unroll
            for (int nt = 0; nt < 8; nt++) {
#pragma unroll
                for (int j = 0; j < 2; j++) {
                    int cl = wcol * 64 + nt * 8 + lane * 2 + j;
                    atomicAdd(&ssum[cl], cs[nt * 2 + j]);
                    atomicAdd(&ssum[256 + cl], cq[nt * 2 + j]);
                }
            }
        }
        __syncthreads();
        if (tid < 256) {
            atomicAdd(gsum + tid, ssum[tid]);
            atomicAdd(gsumsq + tid, ssum[256 + tid]);
        }
    }
}

// ---------------- small fp32 GEMM for lin2 (N=47) ----------------
template<bool RELU>
__global__ void gemm_bias(const float* __restrict__ A, const float* __restrict__ B,
                          const float* __restrict__ bias, float* __restrict__ C,
                          int M, int N, int K) {
    __shared__ float As[16][64];
    __shared__ float Bs[16][64 + 4];
    int tid = threadIdx.x;
    int tx = tid & 15, ty = tid >> 4;
    int bm = blockIdx.x * 64, bn = blockIdx.y * 64;
    float acc[4][4];
#pragma unroll
    for (int i = 0; i < 4; i++)
#pragma unroll
        for (int j = 0; j < 4; j++) acc[i][j] = 0.f;
    for (int kt = 0; kt < K; kt += 16) {
#pragma unroll
        for (int l = 0; l < 4; l++) {
            int idx = tid + l * 256;
            int m = idx >> 4, k = idx & 15;
            int row = bm + m;
            As[k][m] = (row < M) ? A[(size_t)row * K + kt + k] : 0.f;
        }
#pragma unroll
        for (int l = 0; l < 4; l++) {
            int idx = tid + l * 256;
            int k = idx >> 6, n = idx & 63;
            int col = bn + n;
            Bs[k][n] = (col < N) ? B[(size_t)(kt + k) * N + col] : 0.f;
        }
        __syncthreads();
#pragma unroll
        for (int k = 0; k < 16; k++) {
            float a[4], b[4];
#pragma unroll
            for (int i = 0; i < 4; i++) a[i] = As[k][ty * 4 + i];
#pragma unroll
            for (int j = 0; j < 4; j++) b[j] = Bs[k][tx * 4 + j];
#pragma unroll
            for (int i = 0; i < 4; i++)
#pragma unroll
                for (int j = 0; j < 4; j++) acc[i][j] += a[i] * b[j];
        }
        __syncthreads();
    }
#pragma unroll
    for (int i = 0; i < 4; i++) {
        int row = bm + ty * 4 + i;
        if (row >= M) continue;
#pragma unroll
        for (int j = 0; j < 4; j++) {
            int col = bn + tx * 4 + j;
            if (col >= N) continue;
            float v = acc[i][j] + bias[col];
            if (RELU) v = fmaxf(v, 0.f);
            C[(size_t)row * N + col] = v;
        }
    }
}

__global__ void log_softmax47(const float* __restrict__ z, float* __restrict__ out) {
    int r = blockIdx.x;
    int lane = threadIdx.x;
    const float* zr = z + (size_t)r * OUTC;
    float v0 = (lane < OUTC) ? zr[lane] : -INFINITY;
    float v1 = (lane + 32 < OUTC) ? zr[lane + 32] : -INFINITY;
    float m = fmaxf(v0, v1);
#pragma unroll
    for (int o = 16; o > 0; o >>= 1) m = fmaxf(m, __shfl_xor_sync(0xffffffff, m, o));
    float e = ((lane < OUTC) ? expf(v0 - m) : 0.f) + ((lane + 32 < OUTC) ? expf(v1 - m) : 0.f);
#pragma unroll
    for (int o = 16; o > 0; o >>= 1) e += __shfl_xor_sync(0xffffffff, e, o);
    float lse = logf(e) + m;
    if (lane < OUTC) out[(size_t)r * OUTC + lane] = v0 - lse;
    if (lane + 32 < OUTC) out[(size_t)r * OUTC + lane + 32] = v1 - lse;
}

// ---------------- host driver ----------------
extern "C" void kernel_launch(void* const* d_in, const int* in_sizes, int n_in,
                              void* d_out, int out_size) {
    const float* x = (const float*)d_in[0];
    const int* eis[3] = {(const int*)d_in[1], (const int*)d_in[2], (const int*)d_in[3]};
    const float* cw[3][6];
    for (int l = 0; l < 3; l++)
        for (int i = 0; i < 6; i++)
            cw[l][i] = (const float*)d_in[4 + l * 6 + i];
    const float* lin1_w = (const float*)d_in[22];
    const float* lin1_b = (const float*)d_in[23];
    const float* lin2_w = (const float*)d_in[24];
    const float* lin2_b = (const float*)d_in[25];
    float* out = (float*)d_out;

    float *bufA, *bufB, *sum, *sumsq, *scale, *shift;
    __half *wHi, *wLo;
    cudaGetSymbolAddress((void**)&bufA, g_bufA);
    cudaGetSymbolAddress((void**)&bufB, g_bufB);
    cudaGetSymbolAddress((void**)&wHi, g_wHi);
    cudaGetSymbolAddress((void**)&wLo, g_wLo);
    cudaGetSymbolAddress((void**)&sum, g_sum);
    cudaGetSymbolAddress((void**)&sumsq, g_sumsq);
    cudaGetSymbolAddress((void**)&scale, g_scale);
    cudaGetSymbolAddress((void**)&shift, g_shift);

    cudaFuncSetAttribute(gemm_f32a<128, false, false, true>,  cudaFuncAttributeMaxDynamicSharedMemorySize, GEMM_SMEM);
    cudaFuncSetAttribute(gemm_f32a<256, false, false, true>,  cudaFuncAttributeMaxDynamicSharedMemorySize, GEMM_SMEM);
    cudaFuncSetAttribute(gemm_f32a<256, true,  true,  false>, cudaFuncAttributeMaxDynamicSharedMemorySize, GEMM_SMEM);
    cudaFuncSetAttribute(gemm_f32a<256, false, true,  false>, cudaFuncAttributeMaxDynamicSharedMemorySize, GEMM_SMEM);

    const int nt[3] = {N0T, N1T, N2T};
    const int ne[3] = {E0, E1, E2};

    const float* cur = x;
    for (int l = 0; l < 3; l++) {
        int M = nt[l];
        int C = (l == 0) ? C_IN : HID;
        // buffer schedule keeps src/dst disjoint per kernel
        float* Agg = (l == 1) ? bufB : bufA;
        float* H1  = (l == 1) ? bufA : bufB;
        float* H2  = (l == 1) ? bufB : bufA;

        // launch order L0: copy(0), scatter(1), conv_wT+zero(2), gemm1(3) <- profiled
        int n4 = M * C / 4;
        copy_f4<<<min((n4 + 255) / 256, 4096), 256>>>(cur, Agg, n4);
        if (C == 128)
            agg_scatter<128><<<(ne[l] + 7) / 8, 256>>>(cur, eis[l], eis[l] + ne[l], Agg, ne[l]);
        else
            agg_scatter<256><<<(ne[l] + 7) / 8, 256>>>(cur, eis[l], eis[l] + ne[l], Agg, ne[l]);

        conv_wT<<<(C * HID + 255) / 256, 256>>>(cw[l][0], wHi + l * 65536, wLo + l * 65536, C, HID,
                                                (l == 0) ? sum : nullptr, (l == 0) ? sumsq : nullptr);

        // H1 = Agg @ w1 + b1, with fused column stats
        if (C == 128)
            gemm_f32a<128, false, false, true><<<M / 128, 512, GEMM_SMEM>>>(
                Agg, wHi + l * 65536, wLo + l * 65536, nullptr, nullptr, cw[l][1], H1, sum, sumsq);
        else
            gemm_f32a<256, false, false, true><<<M / 128, 512, GEMM_SMEM>>>(
                Agg, wHi + l * 65536, wLo + l * 65536, nullptr, nullptr, cw[l][1], H1, sum, sumsq);

        bn_prep<<<1, HID>>>(sum, sumsq, cw[l][2], cw[l][3], M, scale, shift);
        conv_wT<<<(HID * HID + 255) / 256, 256>>>(cw[l][4], wHi + (3 + l) * 65536, wLo + (3 + l) * 65536, HID, HID, nullptr, nullptr);

        // H2 = relu( relu(BN(H1)) @ w2 + b2 ), BN+ReLU fused at A-load
        gemm_f32a<256, true, true, false><<<M / 128, 512, GEMM_SMEM>>>(
            H1, wHi + (3 + l) * 65536, wLo + (3 + l) * 65536, scale, shift, cw[l][5], H2, nullptr, nullptr);
        cur = H2;
    }

    // head: relu(cur @ lin1 + b) -> bufB ; lin2 -> bufA
    conv_wT<<<(HID * HID + 255) / 256, 256>>>(lin1_w, wHi + 6 * 65536, wLo + 6 * 65536, HID, HID, nullptr, nullptr);
    gemm_f32a<256, false, true, false><<<N2T / 128, 512, GEMM_SMEM>>>(
        cur, wHi + 6 * 65536, wLo + 6 * 65536, nullptr, nullptr, lin1_b, bufB, nullptr, nullptr);
    gemm_bias<false><<<dim3((N2T + 63) / 64, 1), 256>>>(bufB, lin2_w, lin2_b, bufA, N2T, OUTC, HID);
    log_softmax47<<<N2T, 32>>>(bufA, out);
}

// round 9
// speedup vs baseline: 1.0597x; 1.0597x over previous
#include <cuda_runtime.h>
#include <cuda_fp16.h>
#include <math.h>
#include <stdint.h>

// ---------------- problem constants ----------------
#define N0T 123904
#define N1T 11264
#define N2T 1024
#define E0  (N0T*10)
#define E1  (N1T*10)
#define E2  (N2T*10)
#define C_IN 128
#define HID  256
#define OUTC 47
#define BN_EPS 1e-5f

// ---------------- scratch (no allocation allowed) ----------------
__device__ float g_bufA[(size_t)N0T * HID];   // 126.9 MB
__device__ float g_bufB[(size_t)N0T * HID];   // 126.9 MB
__device__ __half g_wHi[7 * 65536];           // transposed weights hi  [N][K]
__device__ __half g_wLo[7 * 65536];           // transposed weights lo
__device__ float g_sum[HID], g_sumsq[HID], g_scale[HID], g_shift[HID];

// ---------------- PTX helpers ----------------
__device__ __forceinline__ uint32_t smem_u32(const void* p) {
    uint32_t a;
    asm("{ .reg .u64 t; cvta.to.shared.u64 t, %1; cvt.u32.u64 %0, t; }" : "=r"(a) : "l"(p));
    return a;
}
__device__ __forceinline__ void ldm_x4(uint32_t* r, uint32_t addr) {
    asm volatile("ldmatrix.sync.aligned.m8n8.x4.shared.b16 {%0,%1,%2,%3}, [%4];"
        : "=r"(r[0]), "=r"(r[1]), "=r"(r[2]), "=r"(r[3]) : "r"(addr));
}
__device__ __forceinline__ void mma16816(float* d, const uint32_t* a, const uint32_t* b) {
    asm volatile("mma.sync.aligned.m16n8k16.row.col.f32.f16.f16.f32 "
        "{%0,%1,%2,%3}, {%4,%5,%6,%7}, {%8,%9}, {%0,%1,%2,%3};"
        : "+f"(d[0]), "+f"(d[1]), "+f"(d[2]), "+f"(d[3])
        : "r"(a[0]), "r"(a[1]), "r"(a[2]), "r"(a[3]), "r"(b[0]), "r"(b[1]));
}
#define CPA16(dst, src) asm volatile("cp.async.cg.shared.global [%0], [%1], 16;" :: "r"(dst), "l"(src))
#define CPA_COMMIT()    asm volatile("cp.async.commit_group;" ::: "memory")
#define CPA_WAIT1()     asm volatile("cp.async.wait_group 1;" ::: "memory")
#define CPA_WAIT0()     asm volatile("cp.async.wait_group 0;" ::: "memory")

// ---------------- misc kernels ----------------
__global__ void copy_f4(const float* __restrict__ in, float* __restrict__ out, int n4) {
    int i = blockIdx.x * blockDim.x + threadIdx.x;
    int stride = gridDim.x * blockDim.x;
    const float4* in4 = (const float4*)in;
    float4* out4 = (float4*)out;
    for (; i < n4; i += stride) out4[i] = in4[i];
}

template<int C>
__global__ void agg_scatter(const float* __restrict__ x, const int* __restrict__ src,
                            const int* __restrict__ tgt, float* __restrict__ agg, int e) {
    int warp = (blockIdx.x * blockDim.x + threadIdx.x) >> 5;
    int lane = threadIdx.x & 31;
    if (warp >= e) return;
    int s = src[warp];
    int t = tgt[warp];
    const float4* xs = (const float4*)(x + (size_t)s * C);
    float* ao = agg + (size_t)t * C;
#pragma unroll
    for (int i = 0; i < C / 128; i++) {
        int q = lane + i * 32;
        float4 v = xs[q];
        int c = q * 4;
        atomicAdd(ao + c + 0, v.x);
        atomicAdd(ao + c + 1, v.y);
        atomicAdd(ao + c + 2, v.z);
        atomicAdd(ao + c + 3, v.w);
    }
}

__device__ __forceinline__ void split2h(float a, float b, uint32_t& hi, uint32_t& lo) {
    __half2 h = __floats2half2_rn(a, b);
    float2 hf = __half22float2(h);
    __half2 l = __floats2half2_rn(a - hf.x, b - hf.y);
    hi = *reinterpret_cast<uint32_t*>(&h);
    lo = *reinterpret_cast<uint32_t*>(&l);
}

// W[K,N] fp32 -> WT hi/lo [N,K] fp16; optionally zero the BN stat accumulators
__global__ void conv_wT(const float* __restrict__ W, __half* __restrict__ hiT,
                        __half* __restrict__ loT, int K, int N,
                        float* __restrict__ zsum, float* __restrict__ zsumsq) {
    int i = blockIdx.x * blockDim.x + threadIdx.x;
    if (zsum && blockIdx.x == 0 && threadIdx.x < HID) {
        zsum[threadIdx.x] = 0.f;
        zsumsq[threadIdx.x] = 0.f;
    }
    if (i >= K * N) return;
    int k = i / N, n = i % N;
    float v = W[i];
    __half h = __float2half_rn(v);
    float rem = v - __half2float(h);
    hiT[(size_t)n * K + k] = h;
    loT[(size_t)n * K + k] = __float2half_rn(rem);
}

// compute scale/shift from stats, then re-zero stats for the next layer
__global__ void bn_prep(float* __restrict__ sum, float* __restrict__ sumsq,
                        const float* __restrict__ g, const float* __restrict__ be,
                        int M, float* __restrict__ scale, float* __restrict__ shift) {
    int c = threadIdx.x;
    float inv = 1.f / (float)M;
    float mu = sum[c] * inv;
    float var = sumsq[c] * inv - mu * mu;
    float sc = g[c] * rsqrtf(var + BN_EPS);
    scale[c] = sc;
    shift[c] = be[c] - mu * sc;
    sum[c] = 0.f;
    sumsq[c] = 0.f;
}

// ---------------- fused mma.sync GEMM, fp32 A input ----------------
// C[M,256] = op(A)[M,KT] @ W[KT,256] + bias ; op(A) = optional BN+ReLU per K-col.
// Software-pipelined: ONE __syncthreads per K-iter; convert(c+1) overlaps mma(c).
// Buffers: fp32 A stage x2 (self-produced via per-thread cp.async wait),
//          converted A16 hi/lo x3, B hi/lo x3.
#define BK 32
#define SPAD 40                          // half-tile row stride (halfs)
#define ATSB (128 * SPAD * 2)            // 10240 B per A16 tile
#define BTSB (256 * SPAD * 2)            // 20480 B per B half tile
#define AF_STRIDE 36                     // fp32 stage row stride (floats)
#define AF_BYTES (128 * AF_STRIDE * 4)   // 18432 B per fp32 stage
#define S_AF 0                           // 2 stages: 36864
#define S_AH (2 * AF_BYTES)              // 36864  (3 bufs: 30720)
#define S_AL (S_AH + 3 * ATSB)           // 67584  (3 bufs: 30720)
#define S_BH (S_AL + 3 * ATSB)           // 98304  (3 stages: 61440)
#define S_BL (S_BH + 3 * BTSB)           // 159744 (3 stages: 61440)
#define S_SS (S_BL + 3 * BTSB)           // 221184
#define GEMM_SMEM (S_SS + 2048)          // 223232

template<int KT, bool BNA, bool RELUOUT, bool STATS>
__global__ void __launch_bounds__(512, 1) gemm_f32a(
    const float* __restrict__ A, const __half* __restrict__ Bhi, const __half* __restrict__ Blo,
    const float* __restrict__ scale, const float* __restrict__ shift,
    const float* __restrict__ bias, float* __restrict__ C,
    float* __restrict__ gsum, float* __restrict__ gsumsq)
{
    extern __shared__ char smem[];
    const uint32_t sb = smem_u32(smem);
    const int tid = threadIdx.x, wid = tid >> 5, lane = tid & 31;
    const int wrow = wid & 3, wcol = wid >> 2;     // 4 row-warps x 4 col-warps
    constexpr int NC = KT / BK;

    const int brow = blockIdx.x * 128;

    const int lr = tid >> 2;          // 0..127  (A loader/converter row)
    const int lq = tid & 3;           // 0..3    (8-float segment)
    const int br = tid >> 1;          // 0..255  (B loader row)
    const int bsg = tid & 1;          // 0..1    (16-half segment)

    float* scale_s = (float*)(smem + S_SS);
    float* shift_s = scale_s + 256;
    if (BNA && tid < 256) {
        scale_s[tid] = scale[tid];
        shift_s[tid] = shift[tid];
    }

    auto load_stage = [&](int c) {
        int stA = c & 1, stB = c % 3;
        // A fp32: 32B per thread (self-consumed later by this thread)
        uint32_t ad = sb + S_AF + stA * AF_BYTES + (uint32_t)(lr * AF_STRIDE + lq * 8) * 4;
        const float* pa = A + (size_t)(brow + lr) * KT + c * BK + lq * 8;
        CPA16(ad, pa); CPA16(ad + 16, pa + 4);
        // B hi/lo: 32B each per thread (256 rows)
        uint32_t bdst = (uint32_t)(br * SPAD + bsg * 16) * 2;
        const __half* pb = Bhi + (size_t)br * KT + c * BK + bsg * 16;
        uint32_t bh = sb + S_BH + stB * BTSB + bdst;
        CPA16(bh, pb); CPA16(bh + 16, pb + 8);
        const __half* pq = Blo + (size_t)br * KT + c * BK + bsg * 16;
        uint32_t bl = sb + S_BL + stB * BTSB + bdst;
        CPA16(bl, pq); CPA16(bl + 16, pq + 8);
        CPA_COMMIT();
    };

    // convert fp32 stage (c&1) -> A16 hi/lo buffer (c%3); reads only self-written
    // fp32 data + (BNA) scale_s/shift_s which require a barrier after init.
    auto convert = [&](int c) {
        const float* af = (const float*)(smem + S_AF + (c & 1) * AF_BYTES);
        int base = lr * AF_STRIDE + lq * 8;
        float v[8];
        float4 t0 = *(const float4*)(af + base);
        float4 t1 = *(const float4*)(af + base + 4);
        v[0] = t0.x; v[1] = t0.y; v[2] = t0.z; v[3] = t0.w;
        v[4] = t1.x; v[5] = t1.y; v[6] = t1.z; v[7] = t1.w;
        if (BNA) {
            int k0 = c * BK + lq * 8;
#pragma unroll
            for (int j = 0; j < 8; j++)
                v[j] = fmaxf(fmaf(v[j], scale_s[k0 + j], shift_s[k0 + j]), 0.f);
        }
        uint32_t h[4], l[4];
#pragma unroll
        for (int i = 0; i < 4; i++) split2h(v[2 * i], v[2 * i + 1], h[i], l[i]);
        int ab = c % 3;
        char* dh = smem + S_AH + ab * ATSB + (size_t)(lr * SPAD + lq * 8) * 2;
        char* dl = smem + S_AL + ab * ATSB + (size_t)(lr * SPAD + lq * 8) * 2;
        *(uint4*)dh = *(uint4*)&h[0];
        *(uint4*)dl = *(uint4*)&l[0];
    };

    float acc[2][8][4];
#pragma unroll
    for (int i = 0; i < 2; i++)
#pragma unroll
        for (int j = 0; j < 8; j++)
#pragma unroll
            for (int k = 0; k < 4; k++) acc[i][j][k] = 0.f;

    const uint32_t a_row = wrow * 32 + (lane & 15);
    const uint32_t a_coloff = (lane >> 4) * 8;
    const uint32_t b_row_l = (lane & 7) + ((lane >> 4) << 3);
    const uint32_t b_coloff = ((lane >> 3) & 1) * 8;

    // prologue: stages 0,1 in flight; convert 0.
    // BNA: barrier so scale_s/shift_s (written by other threads) are visible
    // before convert(0) reads them. (This was the R8 correctness bug.)
    load_stage(0);
    if (NC > 1) { load_stage(1); CPA_WAIT1(); } else { CPA_WAIT0(); }
    if (BNA) __syncthreads();
    convert(0);

#pragma unroll 1
    for (int c = 0; c < NC; c++) {
        // barrier: A16[c%3] converts visible; B[c%3] landed in ALL threads
        // (each thread waited on its own groups <= c before arriving);
        // all mma(c-1) smem reads complete.
        __syncthreads();
        if (c + 2 < NC) load_stage(c + 2);

        const int stB = c % 3, stA16 = c % 3;
        const uint32_t aHiB = sb + S_AH + stA16 * ATSB, aLoB = sb + S_AL + stA16 * ATSB;
        const uint32_t bHiB = sb + S_BH + stB * BTSB;
        const uint32_t bLoB = sb + S_BL + stB * BTSB;

#pragma unroll
        for (int ks = 0; ks < 2; ks++) {
            uint32_t ao = (uint32_t)(a_row * SPAD + ks * 16 + a_coloff) * 2;
            uint32_t ah[2][4], al[2][4];
            ldm_x4(ah[0], aHiB + ao);
            ldm_x4(ah[1], aHiB + ao + 16 * SPAD * 2);
            ldm_x4(al[0], aLoB + ao);
            ldm_x4(al[1], aLoB + ao + 16 * SPAD * 2);

#pragma unroll
            for (int nt = 0; nt < 4; nt++) {
                uint32_t bo = (uint32_t)((wcol * 64 + nt * 16 + b_row_l) * SPAD + ks * 16 + b_coloff) * 2;
                uint32_t bh[4], bl[4];
                ldm_x4(bh, bHiB + bo);
                ldm_x4(bl, bLoB + bo);
#pragma unroll
                for (int mf = 0; mf < 2; mf++) {
                    mma16816(acc[mf][nt * 2 + 0], ah[mf], &bh[0]);
                    mma16816(acc[mf][nt * 2 + 0], ah[mf], &bl[0]);
                    mma16816(acc[mf][nt * 2 + 0], al[mf], &bh[0]);
                    mma16816(acc[mf][nt * 2 + 1], ah[mf], &bh[2]);
                    mma16816(acc[mf][nt * 2 + 1], ah[mf], &bl[2]);
                    mma16816(acc[mf][nt * 2 + 1], al[mf], &bh[2]);
                }
            }
        }

        // pipeline the next conversion (overlaps other warps' mma)
        if (c + 1 < NC) {
            if (c + 2 < NC) CPA_WAIT1(); else CPA_WAIT0();   // own stage c+1 landed
            convert(c + 1);
        }
    }

    // ---------------- epilogue ----------------
    const int row0 = brow + wrow * 32 + (lane >> 2);
    const int col0 = wcol * 64 + (lane & 3) * 2;

    float cs[16], cq[16];
    if (STATS) {
#pragma unroll
        for (int i = 0; i < 16; i++) { cs[i] = 0.f; cq[i] = 0.f; }
    }

#pragma unroll
    for (int mf = 0; mf < 2; mf++) {
#pragma unroll
        for (int nt = 0; nt < 8; nt++) {
            float* d = acc[mf][nt];
            int col = col0 + nt * 8;
            float2 bv = *(const float2*)(bias + col);
            int r0 = row0 + mf * 16;
            float2 v0 = {d[0] + bv.x, d[1] + bv.y};
            float2 v1 = {d[2] + bv.x, d[3] + bv.y};
            if (RELUOUT) {
                v0.x = fmaxf(v0.x, 0.f); v0.y = fmaxf(v0.y, 0.f);
                v1.x = fmaxf(v1.x, 0.f); v1.y = fmaxf(v1.y, 0.f);
            }
            if (STATS) {
                int i0 = nt * 2;
                cs[i0] += v0.x + v1.x;       cq[i0] += v0.x * v0.x + v1.x * v1.x;
                cs[i0 + 1] += v0.y + v1.y;   cq[i0 + 1] += v0.y * v0.y + v1.y * v1.y;
            }
            *(float2*)(C + (size_t)r0 * HID + col) = v0;
            *(float2*)(C + (size_t)(r0 + 8) * HID + col) = v1;
        }
    }

    if (STATS) {
#pragma unroll
        for (int off = 4; off <= 16; off <<= 1) {
#pragma unroll
            for (int i = 0; i < 16; i++) {
                cs[i] += __shfl_xor_sync(0xffffffff, cs[i], off);
                cq[i] += __shfl_xor_sync(0xffffffff, cq[i], off);
            }
        }
        __syncthreads();                       // mainloop smem no longer needed
        float* ssum = (float*)smem;            // [0..255] sum, [256..511] sumsq
        ssum[tid] = 0.f;
        __syncthreads();
        if (lane < 4) {
#pragma unroll
            for (int nt = 0; nt < 8; nt++) {
#pragma unroll
                for (int j = 0; j < 2; j++) {
                    int cl = wcol * 64 + nt * 8 + lane * 2 + j;
                    atomicAdd(&ssum[cl], cs[nt * 2 + j]);
                    atomicAdd(&ssum[256 + cl], cq[nt * 2 + j]);
                }
            }
        }
        __syncthreads();
        if (tid < 256) {
            atomicAdd(gsum + tid, ssum[tid]);
            atomicAdd(gsumsq + tid, ssum[256 + tid]);
        }
    }
}

// ---------------- small fp32 GEMM for lin2 (N=47) ----------------
template<bool RELU>
__global__ void gemm_bias(const float* __restrict__ A, const float* __restrict__ B,
                          const float* __restrict__ bias, float* __restrict__ C,
                          int M, int N, int K) {
    __shared__ float As[16][64];
    __shared__ float Bs[16][64 + 4];
    int tid = threadIdx.x;
    int tx = tid & 15, ty = tid >> 4;
    int bm = blockIdx.x * 64, bn = blockIdx.y * 64;
    float acc[4][4];
#pragma unroll
    for (int i = 0; i < 4; i++)
#pragma unroll
        for (int j = 0; j < 4; j++) acc[i][j] = 0.f;
    for (int kt = 0; kt < K; kt += 16) {
#pragma unroll
        for (int l = 0; l < 4; l++) {
            int idx = tid + l * 256;
            int m = idx >> 4, k = idx & 15;
            int row = bm + m;
            As[k][m] = (row < M) ? A[(size_t)row * K + kt + k] : 0.f;
        }
#pragma unroll
        for (int l = 0; l < 4; l++) {
            int idx = tid + l * 256;
            int k = idx >> 6, n = idx & 63;
            int col = bn + n;
            Bs[k][n] = (col < N) ? B[(size_t)(kt + k) * N + col] : 0.f;
        }
        __syncthreads();
#pragma unroll
        for (int k = 0; k < 16; k++) {
            float a[4], b[4];
#pragma unroll
            for (int i = 0; i < 4; i++) a[i] = As[k][ty * 4 + i];
#pragma unroll
            for (int j = 0; j < 4; j++) b[j] = Bs[k][tx * 4 + j];
#pragma unroll
            for (int i = 0; i < 4; i++)
#pragma unroll
                for (int j = 0; j < 4; j++) acc[i][j] += a[i] * b[j];
        }
        __syncthreads();
    }
#pragma unroll
    for (int i = 0; i < 4; i++) {
        int row = bm + ty * 4 + i;
        if (row >= M) continue;
#pragma unroll
        for (int j = 0; j < 4; j++) {
            int col = bn + tx * 4 + j;
            if (col >= N) continue;
            float v = acc[i][j] + bias[col];
            if (RELU) v = fmaxf(v, 0.f);
            C[(size_t)row * N + col] = v;
        }
    }
}

__global__ void log_softmax47(const float* __restrict__ z, float* __restrict__ out) {
    int r = blockIdx.x;
    int lane = threadIdx.x;
    const float* zr = z + (size_t)r * OUTC;
    float v0 = (lane < OUTC) ? zr[lane] : -INFINITY;
    float v1 = (lane + 32 < OUTC) ? zr[lane + 32] : -INFINITY;
    float m = fmaxf(v0, v1);
#pragma unroll
    for (int o = 16; o > 0; o >>= 1) m = fmaxf(m, __shfl_xor_sync(0xffffffff, m, o));
    float e = ((lane < OUTC) ? expf(v0 - m) : 0.f) + ((lane + 32 < OUTC) ? expf(v1 - m) : 0.f);
#pragma unroll
    for (int o = 16; o > 0; o >>= 1) e += __shfl_xor_sync(0xffffffff, e, o);
    float lse = logf(e) + m;
    if (lane < OUTC) out[(size_t)r * OUTC + lane] = v0 - lse;
    if (lane + 32 < OUTC) out[(size_t)r * OUTC + lane + 32] = v1 - lse;
}

// ---------------- host driver ----------------
extern "C" void kernel_launch(void* const* d_in, const int* in_sizes, int n_in,
                              void* d_out, int out_size) {
    const float* x = (const float*)d_in[0];
    const int* eis[3] = {(const int*)d_in[1], (const int*)d_in[2], (const int*)d_in[3]};
    const float* cw[3][6];
    for (int l = 0; l < 3; l++)
        for (int i = 0; i < 6; i++)
            cw[l][i] = (const float*)d_in[4 + l * 6 + i];
    const float* lin1_w = (const float*)d_in[22];
    const float* lin1_b = (const float*)d_in[23];
    const float* lin2_w = (const float*)d_in[24];
    const float* lin2_b = (const float*)d_in[25];
    float* out = (float*)d_out;

    float *bufA, *bufB, *sum, *sumsq, *scale, *shift;
    __half *wHi, *wLo;
    cudaGetSymbolAddress((void**)&bufA, g_bufA);
    cudaGetSymbolAddress((void**)&bufB, g_bufB);
    cudaGetSymbolAddress((void**)&wHi, g_wHi);
    cudaGetSymbolAddress((void**)&wLo, g_wLo);
    cudaGetSymbolAddress((void**)&sum, g_sum);
    cudaGetSymbolAddress((void**)&sumsq, g_sumsq);
    cudaGetSymbolAddress((void**)&scale, g_scale);
    cudaGetSymbolAddress((void**)&shift, g_shift);

    cudaFuncSetAttribute(gemm_f32a<128, false, false, true>,  cudaFuncAttributeMaxDynamicSharedMemorySize, GEMM_SMEM);
    cudaFuncSetAttribute(gemm_f32a<256, false, false, true>,  cudaFuncAttributeMaxDynamicSharedMemorySize, GEMM_SMEM);
    cudaFuncSetAttribute(gemm_f32a<256, true,  true,  false>, cudaFuncAttributeMaxDynamicSharedMemorySize, GEMM_SMEM);
    cudaFuncSetAttribute(gemm_f32a<256, false, true,  false>, cudaFuncAttributeMaxDynamicSharedMemorySize, GEMM_SMEM);

    const int nt[3] = {N0T, N1T, N2T};
    const int ne[3] = {E0, E1, E2};

    const float* cur = x;
    for (int l = 0; l < 3; l++) {
        int M = nt[l];
        int C = (l == 0) ? C_IN : HID;
        // buffer schedule keeps src/dst disjoint per kernel
        float* Agg = (l == 1) ? bufB : bufA;
        float* H1  = (l == 1) ? bufA : bufB;
        float* H2  = (l == 1) ? bufB : bufA;

        // launch order L0: copy(0), scatter(1), conv_wT+zero(2), gemm1(3) <- profiled
        int n4 = M * C / 4;
        copy_f4<<<min((n4 + 255) / 256, 4096), 256>>>(cur, Agg, n4);
        if (C == 128)
            agg_scatter<128><<<(ne[l] + 7) / 8, 256>>>(cur, eis[l], eis[l] + ne[l], Agg, ne[l]);
        else
            agg_scatter<256><<<(ne[l] + 7) / 8, 256>>>(cur, eis[l], eis[l] + ne[l], Agg, ne[l]);

        conv_wT<<<(C * HID + 255) / 256, 256>>>(cw[l][0], wHi + l * 65536, wLo + l * 65536, C, HID,
                                                (l == 0) ? sum : nullptr, (l == 0) ? sumsq : nullptr);

        // H1 = Agg @ w1 + b1, with fused column stats
        if (C == 128)
            gemm_f32a<128, false, false, true><<<M / 128, 512, GEMM_SMEM>>>(
                Agg, wHi + l * 65536, wLo + l * 65536, nullptr, nullptr, cw[l][1], H1, sum, sumsq);
        else
            gemm_f32a<256, false, false, true><<<M / 128, 512, GEMM_SMEM>>>(
                Agg, wHi + l * 65536, wLo + l * 65536, nullptr, nullptr, cw[l][1], H1, sum, sumsq);

        bn_prep<<<1, HID>>>(sum, sumsq, cw[l][2], cw[l][3], M, scale, shift);
        conv_wT<<<(HID * HID + 255) / 256, 256>>>(cw[l][4], wHi + (3 + l) * 65536, wLo + (3 + l) * 65536, HID, HID, nullptr, nullptr);

        // H2 = relu( relu(BN(H1)) @ w2 + b2 ), BN+ReLU fused at A-load
        gemm_f32a<256, true, true, false><<<M / 128, 512, GEMM_SMEM>>>(
            H1, wHi + (3 + l) * 65536, wLo + (3 + l) * 65536, scale, shift, cw[l][5], H2, nullptr, nullptr);
        cur = H2;
    }

    // head: relu(cur @ lin1 + b) -> bufB ; lin2 -> bufA
    conv_wT<<<(HID * HID + 255) / 256, 256>>>(lin1_w, wHi + 6 * 65536, wLo + 6 * 65536, HID, HID, nullptr, nullptr);
    gemm_f32a<256, false, true, false><<<N2T / 128, 512, GEMM_SMEM>>>(
        cur, wHi + 6 * 65536, wLo + 6 * 65536, nullptr, nullptr, lin1_b, bufB, nullptr, nullptr);
    gemm_bias<false><<<dim3((N2T + 63) / 64, 1), 256>>>(bufB, lin2_w, lin2_b, bufA, N2T, OUTC, HID);
    log_softmax47<<<N2T, 32>>>(bufA, out);
}

// round 10
// speedup vs baseline: 1.0858x; 1.0247x over previous
#include <cuda_runtime.h>
#include <cuda_fp16.h>
#include <math.h>
#include <stdint.h>

// ---------------- problem constants ----------------
#define N0T 123904
#define N1T 11264
#define N2T 1024
#define E0  (N0T*10)
#define E1  (N1T*10)
#define E2  (N2T*10)
#define C_IN 128
#define HID  256
#define OUTC 47
#define BN_EPS 1e-5f

// ---------------- scratch (no allocation allowed) ----------------
__device__ float g_bufA[(size_t)N0T * HID];   // 126.9 MB
__device__ float g_bufB[(size_t)N0T * HID];   // 126.9 MB
__device__ __half g_wHi[7 * 65536];           // transposed weights hi  [N][K]
__device__ __half g_wLo[7 * 65536];           // transposed weights lo
__device__ float g_sum[HID], g_sumsq[HID], g_scale[HID], g_shift[HID];

// ---------------- PTX helpers ----------------
__device__ __forceinline__ uint32_t smem_u32(const void* p) {
    uint32_t a;
    asm("{ .reg .u64 t; cvta.to.shared.u64 t, %1; cvt.u32.u64 %0, t; }" : "=r"(a) : "l"(p));
    return a;
}
__device__ __forceinline__ void ldm_x4(uint32_t* r, uint32_t addr) {
    asm volatile("ldmatrix.sync.aligned.m8n8.x4.shared.b16 {%0,%1,%2,%3}, [%4];"
        : "=r"(r[0]), "=r"(r[1]), "=r"(r[2]), "=r"(r[3]) : "r"(addr));
}
__device__ __forceinline__ void mma16816(float* d, const uint32_t* a, const uint32_t* b) {
    asm volatile("mma.sync.aligned.m16n8k16.row.col.f32.f16.f16.f32 "
        "{%0,%1,%2,%3}, {%4,%5,%6,%7}, {%8,%9}, {%0,%1,%2,%3};"
        : "+f"(d[0]), "+f"(d[1]), "+f"(d[2]), "+f"(d[3])
        : "r"(a[0]), "r"(a[1]), "r"(a[2]), "r"(a[3]), "r"(b[0]), "r"(b[1]));
}
#define CPA16(dst, src) asm volatile("cp.async.cg.shared.global [%0], [%1], 16;" :: "r"(dst), "l"(src))
#define CPA_COMMIT()    asm volatile("cp.async.commit_group;" ::: "memory")
#define CPA_WAIT1()     asm volatile("cp.async.wait_group 1;" ::: "memory")
#define CPA_WAIT0()     asm volatile("cp.async.wait_group 0;" ::: "memory")

// ---------------- misc kernels ----------------
__global__ void copy_f4(const float* __restrict__ in, float* __restrict__ out, int n4) {
    int i = blockIdx.x * blockDim.x + threadIdx.x;
    int stride = gridDim.x * blockDim.x;
    const float4* in4 = (const float4*)in;
    float4* out4 = (float4*)out;
    for (; i < n4; i += stride) out4[i] = in4[i];
}

template<int C>
__global__ void agg_scatter(const float* __restrict__ x, const int* __restrict__ src,
                            const int* __restrict__ tgt, float* __restrict__ agg, int e) {
    int warp = (blockIdx.x * blockDim.x + threadIdx.x) >> 5;
    int lane = threadIdx.x & 31;
    if (warp >= e) return;
    int s = src[warp];
    int t = tgt[warp];
    const float4* xs = (const float4*)(x + (size_t)s * C);
    float* ao = agg + (size_t)t * C;
#pragma unroll
    for (int i = 0; i < C / 128; i++) {
        int q = lane + i * 32;
        float4 v = xs[q];
        int c = q * 4;
        atomicAdd(ao + c + 0, v.x);
        atomicAdd(ao + c + 1, v.y);
        atomicAdd(ao + c + 2, v.z);
        atomicAdd(ao + c + 3, v.w);
    }
}

__device__ __forceinline__ void split2h(float a, float b, uint32_t& hi, uint32_t& lo) {
    __half2 h = __floats2half2_rn(a, b);
    float2 hf = __half22float2(h);
    __half2 l = __floats2half2_rn(a - hf.x, b - hf.y);
    hi = *reinterpret_cast<uint32_t*>(&h);
    lo = *reinterpret_cast<uint32_t*>(&l);
}

// W[K,N] fp32 -> WT hi/lo [N,K] fp16; optionally zero the BN stat accumulators
__global__ void conv_wT(const float* __restrict__ W, __half* __restrict__ hiT,
                        __half* __restrict__ loT, int K, int N,
                        float* __restrict__ zsum, float* __restrict__ zsumsq) {
    int i = blockIdx.x * blockDim.x + threadIdx.x;
    if (zsum && blockIdx.x == 0 && threadIdx.x < HID) {
        zsum[threadIdx.x] = 0.f;
        zsumsq[threadIdx.x] = 0.f;
    }
    if (i >= K * N) return;
    int k = i / N, n = i % N;
    float v = W[i];
    __half h = __float2half_rn(v);
    float rem = v - __half2float(h);
    hiT[(size_t)n * K + k] = h;
    loT[(size_t)n * K + k] = __float2half_rn(rem);
}

// compute scale/shift from stats, then re-zero stats for the next layer
__global__ void bn_prep(float* __restrict__ sum, float* __restrict__ sumsq,
                        const float* __restrict__ g, const float* __restrict__ be,
                        int M, float* __restrict__ scale, float* __restrict__ shift) {
    int c = threadIdx.x;
    float inv = 1.f / (float)M;
    float mu = sum[c] * inv;
    float var = sumsq[c] * inv - mu * mu;
    float sc = g[c] * rsqrtf(var + BN_EPS);
    scale[c] = sc;
    shift[c] = be[c] - mu * sc;
    sum[c] = 0.f;
    sumsq[c] = 0.f;
}

// ---------------- fused mma.sync GEMM, fp32 A input ----------------
// C[M, bcol:bcol+128] = op(A)[M,KT] @ W[KT, bcol:bcol+128] + bias
//   op(A) = optional BN+ReLU per K-col. Optional output ReLU + column stats.
// Tile 128x128x32, 256 threads (8 warps), grid = (M/128, 2).
// A loaded straight to registers (LDG, 1-iter prefetch), converted to fp16
// hi/lo in-reg, stored once to smem. A16 x2 bufs, B x3 stages. 1 barrier/iter.
// smem = 104448 B -> 2 CTAs/SM.
#define BK 32
#define SPAD 40                          // tile row stride (halfs)
#define A16B (128 * SPAD * 2)            // 10240 B per A16 half tile buf
#define BTB  (128 * SPAD * 2)            // 10240 B per B half tile per stage
#define S_AH 0                           // 2 bufs: 20480
#define S_AL (S_AH + 2 * A16B)           // 20480 (2 bufs: 20480)
#define S_BH (S_AL + 2 * A16B)           // 40960 (3 stages: 30720)
#define S_BL (S_BH + 3 * BTB)            // 71680 (3 stages: 30720)
#define S_SS (S_BL + 3 * BTB)            // 102400
#define GEMM_SMEM (S_SS + 2048)          // 104448

template<int KT, bool BNA, bool RELUOUT, bool STATS>
__global__ void __launch_bounds__(256, 2) gemm_f32a(
    const float* __restrict__ A, const __half* __restrict__ Bhi, const __half* __restrict__ Blo,
    const float* __restrict__ scale, const float* __restrict__ shift,
    const float* __restrict__ bias, float* __restrict__ C,
    float* __restrict__ gsum, float* __restrict__ gsumsq)
{
    extern __shared__ char smem[];
    const uint32_t sb = smem_u32(smem);
    const int tid = threadIdx.x, wid = tid >> 5, lane = tid & 31;
    const int wrow = wid & 3, wcol = wid >> 2;     // 4 row-warps x 2 col-warps
    constexpr int NC = KT / BK;

    const int brow = blockIdx.x * 128;
    const int bcol = blockIdx.y * 128;

    const int lr = tid >> 1;          // 0..127  (loader row, A and B)
    const int lg = tid & 1;           // 0..1    (16-elem segment)

    float* scale_s = (float*)(smem + S_SS);
    float* shift_s = scale_s + 256;
    if (BNA && tid < 256) {
        scale_s[tid] = scale[tid];
        shift_s[tid] = shift[tid];
    }

    // B stage load (cp.async, one commit group per call)
    auto load_B = [&](int c) {
        int st = c % 3;
        uint32_t bdst = (uint32_t)(lr * SPAD + lg * 16) * 2;
        const __half* pb = Bhi + (size_t)(bcol + lr) * KT + c * BK + lg * 16;
        uint32_t bh = sb + S_BH + st * BTB + bdst;
        CPA16(bh, pb); CPA16(bh + 16, pb + 8);
        const __half* pq = Blo + (size_t)(bcol + lr) * KT + c * BK + lg * 16;
        uint32_t bl = sb + S_BL + st * BTB + bdst;
        CPA16(bl, pq); CPA16(bl + 16, pq + 8);
        CPA_COMMIT();
    };

    // A register prefetch: 16 floats per thread
    float v[16];
    auto load_A = [&](int c) {
        const float* pa = A + (size_t)(brow + lr) * KT + c * BK + lg * 16;
#pragma unroll
        for (int i = 0; i < 4; i++) {
            float4 t = *(const float4*)(pa + i * 4);
            v[i * 4 + 0] = t.x; v[i * 4 + 1] = t.y; v[i * 4 + 2] = t.z; v[i * 4 + 3] = t.w;
        }
    };

    // convert regs -> A16 hi/lo buffer (c&1); BNA reads scale_s (barrier-protected)
    auto convert = [&](int c) {
        float w[16];
#pragma unroll
        for (int i = 0; i < 16; i++) w[i] = v[i];
        if (BNA) {
            int k0 = c * BK + lg * 16;
#pragma unroll
            for (int j = 0; j < 16; j++)
                w[j] = fmaxf(fmaf(w[j], scale_s[k0 + j], shift_s[k0 + j]), 0.f);
        }
        uint32_t h[8], l[8];
#pragma unroll
        for (int i = 0; i < 8; i++) split2h(w[2 * i], w[2 * i + 1], h[i], l[i]);
        int ab = c & 1;
        char* dh = smem + S_AH + ab * A16B + (size_t)(lr * SPAD + lg * 16) * 2;
        char* dl = smem + S_AL + ab * A16B + (size_t)(lr * SPAD + lg * 16) * 2;
        *(uint4*)dh = *(uint4*)&h[0];
        *(uint4*)(dh + 16) = *(uint4*)&h[4];
        *(uint4*)dl = *(uint4*)&l[0];
        *(uint4*)(dl + 16) = *(uint4*)&l[4];
    };

    float acc[2][8][4];
#pragma unroll
    for (int i = 0; i < 2; i++)
#pragma unroll
        for (int j = 0; j < 8; j++)
#pragma unroll
            for (int k = 0; k < 4; k++) acc[i][j][k] = 0.f;

    const uint32_t a_row = wrow * 32 + (lane & 15);
    const uint32_t a_coloff = (lane >> 4) * 8;
    const uint32_t b_row_l = (lane & 7) + ((lane >> 4) << 3);
    const uint32_t b_coloff = ((lane >> 3) & 1) * 8;

    // prologue: B(0), B(1) in flight; A(0) -> regs -> A16 buf0
    load_A(0);
    load_B(0);
    if (NC > 1) { load_B(1); CPA_WAIT1(); } else { CPA_WAIT0(); }
    if (BNA) __syncthreads();     // scale_s/shift_s visible before convert(0)
    convert(0);

#pragma unroll 1
    for (int c = 0; c < NC; c++) {
        // barrier: A16[c&1] converts visible; B[c%3] landed in all threads
        // (each waited its own groups <= c before arriving); mma(c-1) done.
        __syncthreads();
        if (c + 2 < NC) load_B(c + 2);
        if (c + 1 < NC) load_A(c + 1);

        const uint32_t aHiB = sb + S_AH + (c & 1) * A16B;
        const uint32_t aLoB = sb + S_AL + (c & 1) * A16B;
        const uint32_t bHiB = sb + S_BH + (c % 3) * BTB;
        const uint32_t bLoB = sb + S_BL + (c % 3) * BTB;

#pragma unroll
        for (int ks = 0; ks < 2; ks++) {
            uint32_t ao = (uint32_t)(a_row * SPAD + ks * 16 + a_coloff) * 2;
            uint32_t ah[2][4], al[2][4];
            ldm_x4(ah[0], aHiB + ao);
            ldm_x4(ah[1], aHiB + ao + 16 * SPAD * 2);
            ldm_x4(al[0], aLoB + ao);
            ldm_x4(al[1], aLoB + ao + 16 * SPAD * 2);

#pragma unroll
            for (int nt = 0; nt < 4; nt++) {
                uint32_t bo = (uint32_t)((wcol * 64 + nt * 16 + b_row_l) * SPAD + ks * 16 + b_coloff) * 2;
                uint32_t bh[4], bl[4];
                ldm_x4(bh, bHiB + bo);
                ldm_x4(bl, bLoB + bo);
#pragma unroll
                for (int mf = 0; mf < 2; mf++) {
                    mma16816(acc[mf][nt * 2 + 0], ah[mf], &bh[0]);
                    mma16816(acc[mf][nt * 2 + 0], ah[mf], &bl[0]);
                    mma16816(acc[mf][nt * 2 + 0], al[mf], &bh[0]);
                    mma16816(acc[mf][nt * 2 + 1], ah[mf], &bh[2]);
                    mma16816(acc[mf][nt * 2 + 1], ah[mf], &bl[2]);
                    mma16816(acc[mf][nt * 2 + 1], al[mf], &bh[2]);
                }
            }
        }

        // pipeline next conversion (A regs loaded this iter; LDG latency hidden by mma)
        if (c + 1 < NC) {
            if (c + 2 < NC) CPA_WAIT1(); else CPA_WAIT0();   // B(c+1) landed (own stores)
            convert(c + 1);
        }
    }

    // ---------------- epilogue ----------------
    const int row0 = brow + wrow * 32 + (lane >> 2);
    const int col0 = wcol * 64 + (lane & 3) * 2;

    float cs[16], cq[16];
    if (STATS) {
#pragma unroll
        for (int i = 0; i < 16; i++) { cs[i] = 0.f; cq[i] = 0.f; }
    }

#pragma unroll
    for (int mf = 0; mf < 2; mf++) {
#pragma unroll
        for (int nt = 0; nt < 8; nt++) {
            float* d = acc[mf][nt];
            int col = col0 + nt * 8;
            float2 bv = *(const float2*)(bias + bcol + col);
            int r0 = row0 + mf * 16;
            float2 v0 = {d[0] + bv.x, d[1] + bv.y};
            float2 v1 = {d[2] + bv.x, d[3] + bv.y};
            if (RELUOUT) {
                v0.x = fmaxf(v0.x, 0.f); v0.y = fmaxf(v0.y, 0.f);
                v1.x = fmaxf(v1.x, 0.f); v1.y = fmaxf(v1.y, 0.f);
            }
            if (STATS) {
                int i0 = nt * 2;
                cs[i0] += v0.x + v1.x;       cq[i0] += v0.x * v0.x + v1.x * v1.x;
                cs[i0 + 1] += v0.y + v1.y;   cq[i0 + 1] += v0.y * v0.y + v1.y * v1.y;
            }
            *(float2*)(C + (size_t)r0 * HID + bcol + col) = v0;
            *(float2*)(C + (size_t)(r0 + 8) * HID + bcol + col) = v1;
        }
    }

    if (STATS) {
        // reduce over the 8 lanes sharing the same columns
#pragma unroll
        for (int off = 4; off <= 16; off <<= 1) {
#pragma unroll
            for (int i = 0; i < 16; i++) {
                cs[i] += __shfl_xor_sync(0xffffffff, cs[i], off);
                cq[i] += __shfl_xor_sync(0xffffffff, cq[i], off);
            }
        }
        __syncthreads();                       // mainloop smem no longer needed
        float* ssum = (float*)smem;            // [0..127] sum, [128..255] sumsq
        ssum[tid] = 0.f;
        __syncthreads();
        if (lane < 4) {
#pragma unroll
            for (int nt = 0; nt < 8; nt++) {
#pragma unroll
                for (int j = 0; j < 2; j++) {
                    int cl = wcol * 64 + nt * 8 + lane * 2 + j;
                    atomicAdd(&ssum[cl], cs[nt * 2 + j]);
                    atomicAdd(&ssum[128 + cl], cq[nt * 2 + j]);
                }
            }
        }
        __syncthreads();
        if (tid < 128) {
            atomicAdd(gsum + bcol + tid, ssum[tid]);
            atomicAdd(gsumsq + bcol + tid, ssum[128 + tid]);
        }
    }
}

// ---------------- small fp32 GEMM for lin2 (N=47) ----------------
template<bool RELU>
__global__ void gemm_bias(const float* __restrict__ A, const float* __restrict__ B,
                          const float* __restrict__ bias, float* __restrict__ C,
                          int M, int N, int K) {
    __shared__ float As[16][64];
    __shared__ float Bs[16][64 + 4];
    int tid = threadIdx.x;
    int tx = tid & 15, ty = tid >> 4;
    int bm = blockIdx.x * 64, bn = blockIdx.y * 64;
    float acc[4][4];
#pragma unroll
    for (int i = 0; i < 4; i++)
#pragma unroll
        for (int j = 0; j < 4; j++) acc[i][j] = 0.f;
    for (int kt = 0; kt < K; kt += 16) {
#pragma unroll
        for (int l = 0; l < 4; l++) {
            int idx = tid + l * 256;
            int m = idx >> 4, k = idx & 15;
            int row = bm + m;
            As[k][m] = (row < M) ? A[(size_t)row * K + kt + k] : 0.f;
        }
#pragma unroll
        for (int l = 0; l < 4; l++) {
            int idx = tid + l * 256;
            int k = idx >> 6, n = idx & 63;
            int col = bn + n;
            Bs[k][n] = (col < N) ? B[(size_t)(kt + k) * N + col] : 0.f;
        }
        __syncthreads();
#pragma unroll
        for (int k = 0; k < 16; k++) {
            float a[4], b[4];
#pragma unroll
            for (int i = 0; i < 4; i++) a[i] = As[k][ty * 4 + i];
#pragma unroll
            for (int j = 0; j < 4; j++) b[j] = Bs[k][tx * 4 + j];
#pragma unroll
            for (int i = 0; i < 4; i++)
#pragma unroll
                for (int j = 0; j < 4; j++) acc[i][j] += a[i] * b[j];
        }
        __syncthreads();
    }
#pragma unroll
    for (int i = 0; i < 4; i++) {
        int row = bm + ty * 4 + i;
        if (row >= M) continue;
#pragma unroll
        for (int j = 0; j < 4; j++) {
            int col = bn + tx * 4 + j;
            if (col >= N) continue;
            float v = acc[i][j] + bias[col];
            if (RELU) v = fmaxf(v, 0.f);
            C[(size_t)row * N + col] = v;
        }
    }
}

__global__ void log_softmax47(const float* __restrict__ z, float* __restrict__ out) {
    int r = blockIdx.x;
    int lane = threadIdx.x;
    const float* zr = z + (size_t)r * OUTC;
    float v0 = (lane < OUTC) ? zr[lane] : -INFINITY;
    float v1 = (lane + 32 < OUTC) ? zr[lane + 32] : -INFINITY;
    float m = fmaxf(v0, v1);
#pragma unroll
    for (int o = 16; o > 0; o >>= 1) m = fmaxf(m, __shfl_xor_sync(0xffffffff, m, o));
    float e = ((lane < OUTC) ? expf(v0 - m) : 0.f) + ((lane + 32 < OUTC) ? expf(v1 - m) : 0.f);
#pragma unroll
    for (int o = 16; o > 0; o >>= 1) e += __shfl_xor_sync(0xffffffff, e, o);
    float lse = logf(e) + m;
    if (lane < OUTC) out[(size_t)r * OUTC + lane] = v0 - lse;
    if (lane + 32 < OUTC) out[(size_t)r * OUTC + lane + 32] = v1 - lse;
}

// ---------------- host driver ----------------
extern "C" void kernel_launch(void* const* d_in, const int* in_sizes, int n_in,
                              void* d_out, int out_size) {
    const float* x = (const float*)d_in[0];
    const int* eis[3] = {(const int*)d_in[1], (const int*)d_in[2], (const int*)d_in[3]};
    const float* cw[3][6];
    for (int l = 0; l < 3; l++)
        for (int i = 0; i < 6; i++)
            cw[l][i] = (const float*)d_in[4 + l * 6 + i];
    const float* lin1_w = (const float*)d_in[22];
    const float* lin1_b = (const float*)d_in[23];
    const float* lin2_w = (const float*)d_in[24];
    const float* lin2_b = (const float*)d_in[25];
    float* out = (float*)d_out;

    float *bufA, *bufB, *sum, *sumsq, *scale, *shift;
    __half *wHi, *wLo;
    cudaGetSymbolAddress((void**)&bufA, g_bufA);
    cudaGetSymbolAddress((void**)&bufB, g_bufB);
    cudaGetSymbolAddress((void**)&wHi, g_wHi);
    cudaGetSymbolAddress((void**)&wLo, g_wLo);
    cudaGetSymbolAddress((void**)&sum, g_sum);
    cudaGetSymbolAddress((void**)&sumsq, g_sumsq);
    cudaGetSymbolAddress((void**)&scale, g_scale);
    cudaGetSymbolAddress((void**)&shift, g_shift);

    cudaFuncSetAttribute(gemm_f32a<128, false, false, true>,  cudaFuncAttributeMaxDynamicSharedMemorySize, GEMM_SMEM);
    cudaFuncSetAttribute(gemm_f32a<256, false, false, true>,  cudaFuncAttributeMaxDynamicSharedMemorySize, GEMM_SMEM);
    cudaFuncSetAttribute(gemm_f32a<256, true,  true,  false>, cudaFuncAttributeMaxDynamicSharedMemorySize, GEMM_SMEM);
    cudaFuncSetAttribute(gemm_f32a<256, false, true,  false>, cudaFuncAttributeMaxDynamicSharedMemorySize, GEMM_SMEM);

    const int nt[3] = {N0T, N1T, N2T};
    const int ne[3] = {E0, E1, E2};

    const float* cur = x;
    for (int l = 0; l < 3; l++) {
        int M = nt[l];
        int C = (l == 0) ? C_IN : HID;
        // buffer schedule keeps src/dst disjoint per kernel
        float* Agg = (l == 1) ? bufB : bufA;
        float* H1  = (l == 1) ? bufA : bufB;
        float* H2  = (l == 1) ? bufB : bufA;

        // launch order L0: copy(0), scatter(1), conv_wT+zero(2), gemm1(3) <- profiled
        int n4 = M * C / 4;
        copy_f4<<<min((n4 + 255) / 256, 4096), 256>>>(cur, Agg, n4);
        if (C == 128)
            agg_scatter<128><<<(ne[l] + 7) / 8, 256>>>(cur, eis[l], eis[l] + ne[l], Agg, ne[l]);
        else
            agg_scatter<256><<<(ne[l] + 7) / 8, 256>>>(cur, eis[l], eis[l] + ne[l], Agg, ne[l]);

        conv_wT<<<(C * HID + 255) / 256, 256>>>(cw[l][0], wHi + l * 65536, wLo + l * 65536, C, HID,
                                                (l == 0) ? sum : nullptr, (l == 0) ? sumsq : nullptr);

        // H1 = Agg @ w1 + b1, with fused column stats
        if (C == 128)
            gemm_f32a<128, false, false, true><<<dim3(M / 128, 2), 256, GEMM_SMEM>>>(
                Agg, wHi + l * 65536, wLo + l * 65536, nullptr, nullptr, cw[l][1], H1, sum, sumsq);
        else
            gemm_f32a<256, false, false, true><<<dim3(M / 128, 2), 256, GEMM_SMEM>>>(
                Agg, wHi + l * 65536, wLo + l * 65536, nullptr, nullptr, cw[l][1], H1, sum, sumsq);

        bn_prep<<<1, HID>>>(sum, sumsq, cw[l][2], cw[l][3], M, scale, shift);
        conv_wT<<<(HID * HID + 255) / 256, 256>>>(cw[l][4], wHi + (3 + l) * 65536, wLo + (3 + l) * 65536, HID, HID, nullptr, nullptr);

        // H2 = relu( relu(BN(H1)) @ w2 + b2 ), BN+ReLU fused at A-load
        gemm_f32a<256, true, true, false><<<dim3(M / 128, 2), 256, GEMM_SMEM>>>(
            H1, wHi + (3 + l) * 65536, wLo + (3 + l) * 65536, scale, shift, cw[l][5], H2, nullptr, nullptr);
        cur = H2;
    }

    // head: relu(cur @ lin1 + b) -> bufB ; lin2 -> bufA
    conv_wT<<<(HID * HID + 255) / 256, 256>>>(lin1_w, wHi + 6 * 65536, wLo + 6 * 65536, HID, HID, nullptr, nullptr);
    gemm_f32a<256, false, true, false><<<dim3(N2T / 128, 2), 256, GEMM_SMEM>>>(
        cur, wHi + 6 * 65536, wLo + 6 * 65536, nullptr, nullptr, lin1_b, bufB, nullptr, nullptr);
    gemm_bias<false><<<dim3((N2T + 63) / 64, 1), 256>>>(bufB, lin2_w, lin2_b, bufA, N2T, OUTC, HID);
    log_softmax47<<<N2T, 32>>>(bufA, out);
}

// round 11
// speedup vs baseline: 1.2339x; 1.1364x over previous
#include <cuda_runtime.h>
#include <cuda_fp16.h>
#include <math.h>
#include <stdint.h>

// ---------------- problem constants ----------------
#define N0T 123904
#define N1T 11264
#define N2T 1024
#define E0  (N0T*10)
#define E1  (N1T*10)
#define E2  (N2T*10)
#define C_IN 128
#define HID  256
#define OUTC 47
#define BN_EPS 1e-5f

// ---------------- scratch (no allocation allowed) ----------------
__device__ float g_bufA[(size_t)N0T * HID];   // 126.9 MB
__device__ float g_bufB[(size_t)N0T * HID];   // 126.9 MB
__device__ __half g_wHi[7 * 65536];           // transposed weights fp16 [N][K]
__device__ float g_sum[HID], g_sumsq[HID], g_scale[HID], g_shift[HID];

// ---------------- PTX helpers ----------------
__device__ __forceinline__ uint32_t smem_u32(const void* p) {
    uint32_t a;
    asm("{ .reg .u64 t; cvta.to.shared.u64 t, %1; cvt.u32.u64 %0, t; }" : "=r"(a) : "l"(p));
    return a;
}
__device__ __forceinline__ void ldm_x4(uint32_t* r, uint32_t addr) {
    asm volatile("ldmatrix.sync.aligned.m8n8.x4.shared.b16 {%0,%1,%2,%3}, [%4];"
        : "=r"(r[0]), "=r"(r[1]), "=r"(r[2]), "=r"(r[3]) : "r"(addr));
}
__device__ __forceinline__ void mma16816(float* d, const uint32_t* a, const uint32_t* b) {
    asm volatile("mma.sync.aligned.m16n8k16.row.col.f32.f16.f16.f32 "
        "{%0,%1,%2,%3}, {%4,%5,%6,%7}, {%8,%9}, {%0,%1,%2,%3};"
        : "+f"(d[0]), "+f"(d[1]), "+f"(d[2]), "+f"(d[3])
        : "r"(a[0]), "r"(a[1]), "r"(a[2]), "r"(a[3]), "r"(b[0]), "r"(b[1]));
}
#define CPA16(dst, src) asm volatile("cp.async.cg.shared.global [%0], [%1], 16;" :: "r"(dst), "l"(src))
#define CPA_COMMIT()    asm volatile("cp.async.commit_group;" ::: "memory")
#define CPA_WAIT1()     asm volatile("cp.async.wait_group 1;" ::: "memory")
#define CPA_WAIT0()     asm volatile("cp.async.wait_group 0;" ::: "memory")

// ---------------- misc kernels ----------------
__global__ void copy_f4(const float* __restrict__ in, float* __restrict__ out, int n4) {
    int i = blockIdx.x * blockDim.x + threadIdx.x;
    int stride = gridDim.x * blockDim.x;
    const float4* in4 = (const float4*)in;
    float4* out4 = (float4*)out;
    for (; i < n4; i += stride) out4[i] = in4[i];
}

template<int C>
__global__ void agg_scatter(const float* __restrict__ x, const int* __restrict__ src,
                            const int* __restrict__ tgt, float* __restrict__ agg, int e) {
    int warp = (blockIdx.x * blockDim.x + threadIdx.x) >> 5;
    int lane = threadIdx.x & 31;
    if (warp >= e) return;
    int s = src[warp];
    int t = tgt[warp];
    const float4* xs = (const float4*)(x + (size_t)s * C);
    float* ao = agg + (size_t)t * C;
#pragma unroll
    for (int i = 0; i < C / 128; i++) {
        int q = lane + i * 32;
        float4 v = xs[q];
        int c = q * 4;
        atomicAdd(ao + c + 0, v.x);
        atomicAdd(ao + c + 1, v.y);
        atomicAdd(ao + c + 2, v.z);
        atomicAdd(ao + c + 3, v.w);
    }
}

__device__ __forceinline__ void split2h(float a, float b, uint32_t& hi, uint32_t& lo) {
    __half2 h = __floats2half2_rn(a, b);
    float2 hf = __half22float2(h);
    __half2 l = __floats2half2_rn(a - hf.x, b - hf.y);
    hi = *reinterpret_cast<uint32_t*>(&h);
    lo = *reinterpret_cast<uint32_t*>(&l);
}

// W[K,N] fp32 -> WT fp16 [N,K]; optionally zero the BN stat accumulators
__global__ void conv_wT(const float* __restrict__ W, __half* __restrict__ hiT,
                        int K, int N, float* __restrict__ zsum, float* __restrict__ zsumsq) {
    int i = blockIdx.x * blockDim.x + threadIdx.x;
    if (zsum && blockIdx.x == 0 && threadIdx.x < HID) {
        zsum[threadIdx.x] = 0.f;
        zsumsq[threadIdx.x] = 0.f;
    }
    if (i >= K * N) return;
    int k = i / N, n = i % N;
    hiT[(size_t)n * K + k] = __float2half_rn(W[i]);
}

// compute scale/shift from stats, then re-zero stats for the next layer
__global__ void bn_prep(float* __restrict__ sum, float* __restrict__ sumsq,
                        const float* __restrict__ g, const float* __restrict__ be,
                        int M, float* __restrict__ scale, float* __restrict__ shift) {
    int c = threadIdx.x;
    float inv = 1.f / (float)M;
    float mu = sum[c] * inv;
    float var = sumsq[c] * inv - mu * mu;
    float sc = g[c] * rsqrtf(var + BN_EPS);
    scale[c] = sc;
    shift[c] = be[c] - mu * sc;
    sum[c] = 0.f;
    sumsq[c] = 0.f;
}

// ---------------- fused mma.sync GEMM, fp32 A input ----------------
// C[M, bcol:bcol+128] = op(A)[M,KT] @ W[KT, bcol:bcol+128] + bias
//   op(A) = optional BN+ReLU per K-col. Optional output ReLU + column stats.
// Split-precision: A = Ahi + Alo (fp16 pair); B single fp16 (rounding error
// ~2^-12 -> dropped A·Blo term ~1.4e-4 rel per GEMM, within tolerance).
// Tile 128x128x32, 256 threads (8 warps), grid = (M/128, 2), 2 CTAs/SM.
// A loaded to regs (LDG, 1-iter prefetch), converted in-reg, stored to smem.
// A16 x2 bufs, B x3 stages, 1 barrier/iter. smem = 73728 B.
#define BK 32
#define SPAD 40                          // tile row stride (halfs)
#define A16B (128 * SPAD * 2)            // 10240 B per A16 half tile buf
#define BTB  (128 * SPAD * 2)            // 10240 B per B tile per stage
#define S_AH 0                           // 2 bufs: 20480
#define S_AL (S_AH + 2 * A16B)           // 20480 (2 bufs: 20480)
#define S_BH (S_AL + 2 * A16B)           // 40960 (3 stages: 30720)
#define S_SS (S_BH + 3 * BTB)            // 71680
#define GEMM_SMEM (S_SS + 2048)          // 73728

template<int KT, bool BNA, bool RELUOUT, bool STATS>
__global__ void __launch_bounds__(256, 2) gemm_f32a(
    const float* __restrict__ A, const __half* __restrict__ Bhi,
    const float* __restrict__ scale, const float* __restrict__ shift,
    const float* __restrict__ bias, float* __restrict__ C,
    float* __restrict__ gsum, float* __restrict__ gsumsq)
{
    extern __shared__ char smem[];
    const uint32_t sb = smem_u32(smem);
    const int tid = threadIdx.x, wid = tid >> 5, lane = tid & 31;
    const int wrow = wid & 3, wcol = wid >> 2;     // 4 row-warps x 2 col-warps
    constexpr int NC = KT / BK;

    const int brow = blockIdx.x * 128;
    const int bcol = blockIdx.y * 128;

    const int lr = tid >> 1;          // 0..127  (loader row, A and B)
    const int lg = tid & 1;           // 0..1    (16-elem segment)

    float* scale_s = (float*)(smem + S_SS);
    float* shift_s = scale_s + 256;
    if (BNA && tid < 256) {
        scale_s[tid] = scale[tid];
        shift_s[tid] = shift[tid];
    }

    // B stage load (cp.async, one commit group per call)
    auto load_B = [&](int c) {
        int st = c % 3;
        uint32_t bdst = (uint32_t)(lr * SPAD + lg * 16) * 2;
        const __half* pb = Bhi + (size_t)(bcol + lr) * KT + c * BK + lg * 16;
        uint32_t bh = sb + S_BH + st * BTB + bdst;
        CPA16(bh, pb); CPA16(bh + 16, pb + 8);
        CPA_COMMIT();
    };

    // A register prefetch: 16 floats per thread
    float v[16];
    auto load_A = [&](int c) {
        const float* pa = A + (size_t)(brow + lr) * KT + c * BK + lg * 16;
#pragma unroll
        for (int i = 0; i < 4; i++) {
            float4 t = *(const float4*)(pa + i * 4);
            v[i * 4 + 0] = t.x; v[i * 4 + 1] = t.y; v[i * 4 + 2] = t.z; v[i * 4 + 3] = t.w;
        }
    };

    // convert regs -> A16 hi/lo buffer (c&1); BNA reads scale_s (barrier-protected)
    auto convert = [&](int c) {
        float w[16];
#pragma unroll
        for (int i = 0; i < 16; i++) w[i] = v[i];
        if (BNA) {
            int k0 = c * BK + lg * 16;
#pragma unroll
            for (int j = 0; j < 16; j++)
                w[j] = fmaxf(fmaf(w[j], scale_s[k0 + j], shift_s[k0 + j]), 0.f);
        }
        uint32_t h[8], l[8];
#pragma unroll
        for (int i = 0; i < 8; i++) split2h(w[2 * i], w[2 * i + 1], h[i], l[i]);
        int ab = c & 1;
        char* dh = smem + S_AH + ab * A16B + (size_t)(lr * SPAD + lg * 16) * 2;
        char* dl = smem + S_AL + ab * A16B + (size_t)(lr * SPAD + lg * 16) * 2;
        *(uint4*)dh = *(uint4*)&h[0];
        *(uint4*)(dh + 16) = *(uint4*)&h[4];
        *(uint4*)dl = *(uint4*)&l[0];
        *(uint4*)(dl + 16) = *(uint4*)&l[4];
    };

    float acc[2][8][4];
#pragma unroll
    for (int i = 0; i < 2; i++)
#pragma unroll
        for (int j = 0; j < 8; j++)
#pragma unroll
            for (int k = 0; k < 4; k++) acc[i][j][k] = 0.f;

    const uint32_t a_row = wrow * 32 + (lane & 15);
    const uint32_t a_coloff = (lane >> 4) * 8;
    const uint32_t b_row_l = (lane & 7) + ((lane >> 4) << 3);
    const uint32_t b_coloff = ((lane >> 3) & 1) * 8;

    // prologue: B(0), B(1) in flight; A(0) -> regs -> A16 buf0
    load_A(0);
    load_B(0);
    if (NC > 1) { load_B(1); CPA_WAIT1(); } else { CPA_WAIT0(); }
    if (BNA) __syncthreads();     // scale_s/shift_s visible before convert(0)
    convert(0);

#pragma unroll 1
    for (int c = 0; c < NC; c++) {
        // barrier: A16[c&1] converts visible; B[c%3] landed in all threads
        // (each waited its own groups <= c before arriving); mma(c-1) done.
        __syncthreads();
        if (c + 2 < NC) load_B(c + 2);
        if (c + 1 < NC) load_A(c + 1);

        const uint32_t aHiB = sb + S_AH + (c & 1) * A16B;
        const uint32_t aLoB = sb + S_AL + (c & 1) * A16B;
        const uint32_t bHiB = sb + S_BH + (c % 3) * BTB;

#pragma unroll
        for (int ks = 0; ks < 2; ks++) {
            uint32_t ao = (uint32_t)(a_row * SPAD + ks * 16 + a_coloff) * 2;
            uint32_t ah[2][4], al[2][4];
            ldm_x4(ah[0], aHiB + ao);
            ldm_x4(ah[1], aHiB + ao + 16 * SPAD * 2);
            ldm_x4(al[0], aLoB + ao);
            ldm_x4(al[1], aLoB + ao + 16 * SPAD * 2);

#pragma unroll
            for (int nt = 0; nt < 4; nt++) {
                uint32_t bo = (uint32_t)((wcol * 64 + nt * 16 + b_row_l) * SPAD + ks * 16 + b_coloff) * 2;
                uint32_t bh[4];
                ldm_x4(bh, bHiB + bo);
#pragma unroll
                for (int mf = 0; mf < 2; mf++) {
                    mma16816(acc[mf][nt * 2 + 0], ah[mf], &bh[0]);
                    mma16816(acc[mf][nt * 2 + 0], al[mf], &bh[0]);
                    mma16816(acc[mf][nt * 2 + 1], ah[mf], &bh[2]);
                    mma16816(acc[mf][nt * 2 + 1], al[mf], &bh[2]);
                }
            }
        }

        // pipeline next conversion (A regs loaded this iter; LDG latency hidden by mma)
        if (c + 1 < NC) {
            if (c + 2 < NC) CPA_WAIT1(); else CPA_WAIT0();   // B(c+1) landed (own stores)
            convert(c + 1);
        }
    }

    // ---------------- epilogue ----------------
    const int row0 = brow + wrow * 32 + (lane >> 2);
    const int col0 = wcol * 64 + (lane & 3) * 2;

    float cs[16], cq[16];
    if (STATS) {
#pragma unroll
        for (int i = 0; i < 16; i++) { cs[i] = 0.f; cq[i] = 0.f; }
    }

#pragma unroll
    for (int mf = 0; mf < 2; mf++) {
#pragma unroll
        for (int nt = 0; nt < 8; nt++) {
            float* d = acc[mf][nt];
            int col = col0 + nt * 8;
            float2 bv = *(const float2*)(bias + bcol + col);
            int r0 = row0 + mf * 16;
            float2 v0 = {d[0] + bv.x, d[1] + bv.y};
            float2 v1 = {d[2] + bv.x, d[3] + bv.y};
            if (RELUOUT) {
                v0.x = fmaxf(v0.x, 0.f); v0.y = fmaxf(v0.y, 0.f);
                v1.x = fmaxf(v1.x, 0.f); v1.y = fmaxf(v1.y, 0.f);
            }
            if (STATS) {
                int i0 = nt * 2;
                cs[i0] += v0.x + v1.x;       cq[i0] += v0.x * v0.x + v1.x * v1.x;
                cs[i0 + 1] += v0.y + v1.y;   cq[i0 + 1] += v0.y * v0.y + v1.y * v1.y;
            }
            *(float2*)(C + (size_t)r0 * HID + bcol + col) = v0;
            *(float2*)(C + (size_t)(r0 + 8) * HID + bcol + col) = v1;
        }
    }

    if (STATS) {
        // reduce over the 8 lanes sharing the same columns
#pragma unroll
        for (int off = 4; off <= 16; off <<= 1) {
#pragma unroll
            for (int i = 0; i < 16; i++) {
                cs[i] += __shfl_xor_sync(0xffffffff, cs[i], off);
                cq[i] += __shfl_xor_sync(0xffffffff, cq[i], off);
            }
        }
        __syncthreads();                       // mainloop smem no longer needed
        float* ssum = (float*)smem;            // [0..127] sum, [128..255] sumsq
        ssum[tid] = 0.f;
        __syncthreads();
        if (lane < 4) {
#pragma unroll
            for (int nt = 0; nt < 8; nt++) {
#pragma unroll
                for (int j = 0; j < 2; j++) {
                    int cl = wcol * 64 + nt * 8 + lane * 2 + j;
                    atomicAdd(&ssum[cl], cs[nt * 2 + j]);
                    atomicAdd(&ssum[128 + cl], cq[nt * 2 + j]);
                }
            }
        }
        __syncthreads();
        if (tid < 128) {
            atomicAdd(gsum + bcol + tid, ssum[tid]);
            atomicAdd(gsumsq + bcol + tid, ssum[128 + tid]);
        }
    }
}

// ---------------- small fp32 GEMM for lin2 (N=47) ----------------
template<bool RELU>
__global__ void gemm_bias(const float* __restrict__ A, const float* __restrict__ B,
                          const float* __restrict__ bias, float* __restrict__ C,
                          int M, int N, int K) {
    __shared__ float As[16][64];
    __shared__ float Bs[16][64 + 4];
    int tid = threadIdx.x;
    int tx = tid & 15, ty = tid >> 4;
    int bm = blockIdx.x * 64, bn = blockIdx.y * 64;
    float acc[4][4];
#pragma unroll
    for (int i = 0; i < 4; i++)
#pragma unroll
        for (int j = 0; j < 4; j++) acc[i][j] = 0.f;
    for (int kt = 0; kt < K; kt += 16) {
#pragma unroll
        for (int l = 0; l < 4; l++) {
            int idx = tid + l * 256;
            int m = idx >> 4, k = idx & 15;
            int row = bm + m;
            As[k][m] = (row < M) ? A[(size_t)row * K + kt + k] : 0.f;
        }
#pragma unroll
        for (int l = 0; l < 4; l++) {
            int idx = tid + l * 256;
            int k = idx >> 6, n = idx & 63;
            int col = bn + n;
            Bs[k][n] = (col < N) ? B[(size_t)(kt + k) * N + col] : 0.f;
        }
        __syncthreads();
#pragma unroll
        for (int k = 0; k < 16; k++) {
            float a[4], b[4];
#pragma unroll
            for (int i = 0; i < 4; i++) a[i] = As[k][ty * 4 + i];
#pragma unroll
            for (int j = 0; j < 4; j++) b[j] = Bs[k][tx * 4 + j];
#pragma unroll
            for (int i = 0; i < 4; i++)
#pragma unroll
                for (int j = 0; j < 4; j++) acc[i][j] += a[i] * b[j];
        }
        __syncthreads();
    }
#pragma unroll
    for (int i = 0; i < 4; i++) {
        int row = bm + ty * 4 + i;
        if (row >= M) continue;
#pragma unroll
        for (int j = 0; j < 4; j++) {
            int col = bn + tx * 4 + j;
            if (col >= N) continue;
            float v = acc[i][j] + bias[col];
            if (RELU) v = fmaxf(v, 0.f);
            C[(size_t)row * N + col] = v;
        }
    }
}

__global__ void log_softmax47(const float* __restrict__ z, float* __restrict__ out) {
    int r = blockIdx.x;
    int lane = threadIdx.x;
    const float* zr = z + (size_t)r * OUTC;
    float v0 = (lane < OUTC) ? zr[lane] : -INFINITY;
    float v1 = (lane + 32 < OUTC) ? zr[lane + 32] : -INFINITY;
    float m = fmaxf(v0, v1);
#pragma unroll
    for (int o = 16; o > 0; o >>= 1) m = fmaxf(m, __shfl_xor_sync(0xffffffff, m, o));
    float e = ((lane < OUTC) ? expf(v0 - m) : 0.f) + ((lane + 32 < OUTC) ? expf(v1 - m) : 0.f);
#pragma unroll
    for (int o = 16; o > 0; o >>= 1) e += __shfl_xor_sync(0xffffffff, e, o);
    float lse = logf(e) + m;
    if (lane < OUTC) out[(size_t)r * OUTC + lane] = v0 - lse;
    if (lane + 32 < OUTC) out[(size_t)r * OUTC + lane + 32] = v1 - lse;
}

// ---------------- host driver ----------------
extern "C" void kernel_launch(void* const* d_in, const int* in_sizes, int n_in,
                              void* d_out, int out_size) {
    const float* x = (const float*)d_in[0];
    const int* eis[3] = {(const int*)d_in[1], (const int*)d_in[2], (const int*)d_in[3]};
    const float* cw[3][6];
    for (int l = 0; l < 3; l++)
        for (int i = 0; i < 6; i++)
            cw[l][i] = (const float*)d_in[4 + l * 6 + i];
    const float* lin1_w = (const float*)d_in[22];
    const float* lin1_b = (const float*)d_in[23];
    const float* lin2_w = (const float*)d_in[24];
    const float* lin2_b = (const float*)d_in[25];
    float* out = (float*)d_out;

    float *bufA, *bufB, *sum, *sumsq, *scale, *shift;
    __half *wHi;
    cudaGetSymbolAddress((void**)&bufA, g_bufA);
    cudaGetSymbolAddress((void**)&bufB, g_bufB);
    cudaGetSymbolAddress((void**)&wHi, g_wHi);
    cudaGetSymbolAddress((void**)&sum, g_sum);
    cudaGetSymbolAddress((void**)&sumsq, g_sumsq);
    cudaGetSymbolAddress((void**)&scale, g_scale);
    cudaGetSymbolAddress((void**)&shift, g_shift);

    cudaFuncSetAttribute(gemm_f32a<128, false, false, true>,  cudaFuncAttributeMaxDynamicSharedMemorySize, GEMM_SMEM);
    cudaFuncSetAttribute(gemm_f32a<256, false, false, true>,  cudaFuncAttributeMaxDynamicSharedMemorySize, GEMM_SMEM);
    cudaFuncSetAttribute(gemm_f32a<256, true,  true,  false>, cudaFuncAttributeMaxDynamicSharedMemorySize, GEMM_SMEM);
    cudaFuncSetAttribute(gemm_f32a<256, false, true,  false>, cudaFuncAttributeMaxDynamicSharedMemorySize, GEMM_SMEM);

    const int nt[3] = {N0T, N1T, N2T};
    const int ne[3] = {E0, E1, E2};

    const float* cur = x;
    for (int l = 0; l < 3; l++) {
        int M = nt[l];
        int C = (l == 0) ? C_IN : HID;
        // buffer schedule keeps src/dst disjoint per kernel
        float* Agg = (l == 1) ? bufB : bufA;
        float* H1  = (l == 1) ? bufA : bufB;
        float* H2  = (l == 1) ? bufB : bufA;

        // launch order L0: copy(0), scatter(1), conv_wT+zero(2), gemm1(3) <- profiled
        int n4 = M * C / 4;
        copy_f4<<<min((n4 + 255) / 256, 4096), 256>>>(cur, Agg, n4);
        if (C == 128)
            agg_scatter<128><<<(ne[l] + 7) / 8, 256>>>(cur, eis[l], eis[l] + ne[l], Agg, ne[l]);
        else
            agg_scatter<256><<<(ne[l] + 7) / 8, 256>>>(cur, eis[l], eis[l] + ne[l], Agg, ne[l]);

        conv_wT<<<(C * HID + 255) / 256, 256>>>(cw[l][0], wHi + l * 65536, C, HID,
                                                (l == 0) ? sum : nullptr, (l == 0) ? sumsq : nullptr);

        // H1 = Agg @ w1 + b1, with fused column stats
        if (C == 128)
            gemm_f32a<128, false, false, true><<<dim3(M / 128, 2), 256, GEMM_SMEM>>>(
                Agg, wHi + l * 65536, nullptr, nullptr, cw[l][1], H1, sum, sumsq);
        else
            gemm_f32a<256, false, false, true><<<dim3(M / 128, 2), 256, GEMM_SMEM>>>(
                Agg, wHi + l * 65536, nullptr, nullptr, cw[l][1], H1, sum, sumsq);

        bn_prep<<<1, HID>>>(sum, sumsq, cw[l][2], cw[l][3], M, scale, shift);
        conv_wT<<<(HID * HID + 255) / 256, 256>>>(cw[l][4], wHi + (3 + l) * 65536, HID, HID, nullptr, nullptr);

        // H2 = relu( relu(BN(H1)) @ w2 + b2 ), BN+ReLU fused at A-load
        gemm_f32a<256, true, true, false><<<dim3(M / 128, 2), 256, GEMM_SMEM>>>(
            H1, wHi + (3 + l) * 65536, scale, shift, cw[l][5], H2, nullptr, nullptr);
        cur = H2;
    }

    // head: relu(cur @ lin1 + b) -> bufB ; lin2 -> bufA
    conv_wT<<<(HID * HID + 255) / 256, 256>>>(lin1_w, wHi + 6 * 65536, HID, HID, nullptr, nullptr);
    gemm_f32a<256, false, true, false><<<dim3(N2T / 128, 2), 256, GEMM_SMEM>>>(
        cur, wHi + 6 * 65536, nullptr, nullptr, lin1_b, bufB, nullptr, nullptr);
    gemm_bias<false><<<dim3((N2T + 63) / 64, 1), 256>>>(bufB, lin2_w, lin2_b, bufA, N2T, OUTC, HID);
    log_softmax47<<<N2T, 32>>>(bufA, out);
}

// round 12
// speedup vs baseline: 1.2860x; 1.0423x over previous
#include <cuda_runtime.h>
#include <cuda_fp16.h>
#include <math.h>
#include <stdint.h>

// ---------------- problem constants ----------------
#define N0T 123904
#define N1T 11264
#define N2T 1024
#define E0  (N0T*10)
#define E1  (N1T*10)
#define E2  (N2T*10)
#define C_IN 128
#define HID  256
#define OUTC 47
#define BN_EPS 1e-5f

// ---------------- scratch (no allocation allowed) ----------------
__device__ float g_bufA[(size_t)N0T * HID];   // 126.9 MB
__device__ float g_bufB[(size_t)N0T * HID];   // 126.9 MB
__device__ __half g_wHi[7 * 65536];           // transposed weights fp16 [N][K]
__device__ float g_sum[HID], g_sumsq[HID], g_scale[HID], g_shift[HID];

// ---------------- PTX helpers ----------------
__device__ __forceinline__ uint32_t smem_u32(const void* p) {
    uint32_t a;
    asm("{ .reg .u64 t; cvta.to.shared.u64 t, %1; cvt.u32.u64 %0, t; }" : "=r"(a) : "l"(p));
    return a;
}
__device__ __forceinline__ void ldm_x4(uint32_t* r, uint32_t addr) {
    asm volatile("ldmatrix.sync.aligned.m8n8.x4.shared.b16 {%0,%1,%2,%3}, [%4];"
        : "=r"(r[0]), "=r"(r[1]), "=r"(r[2]), "=r"(r[3]) : "r"(addr));
}
__device__ __forceinline__ void mma16816(float* d, const uint32_t* a, const uint32_t* b) {
    asm volatile("mma.sync.aligned.m16n8k16.row.col.f32.f16.f16.f32 "
        "{%0,%1,%2,%3}, {%4,%5,%6,%7}, {%8,%9}, {%0,%1,%2,%3};"
        : "+f"(d[0]), "+f"(d[1]), "+f"(d[2]), "+f"(d[3])
        : "r"(a[0]), "r"(a[1]), "r"(a[2]), "r"(a[3]), "r"(b[0]), "r"(b[1]));
}
#define CPA16(dst, src) asm volatile("cp.async.cg.shared.global [%0], [%1], 16;" :: "r"(dst), "l"(src))
#define CPA_COMMIT()    asm volatile("cp.async.commit_group;" ::: "memory")
#define CPA_WAIT1()     asm volatile("cp.async.wait_group 1;" ::: "memory")
#define CPA_WAIT0()     asm volatile("cp.async.wait_group 0;" ::: "memory")

// ---------------- misc kernels ----------------
__global__ void copy_f4(const float* __restrict__ in, float* __restrict__ out, int n4) {
    int i = blockIdx.x * blockDim.x + threadIdx.x;
    int stride = gridDim.x * blockDim.x;
    const float4* in4 = (const float4*)in;
    float4* out4 = (float4*)out;
    for (; i < n4; i += stride) out4[i] = in4[i];
}

template<int C>
__global__ void agg_scatter(const float* __restrict__ x, const int* __restrict__ src,
                            const int* __restrict__ tgt, float* __restrict__ agg, int e) {
    int warp = (blockIdx.x * blockDim.x + threadIdx.x) >> 5;
    int lane = threadIdx.x & 31;
    if (warp >= e) return;
    int s = src[warp];
    int t = tgt[warp];
    const float4* xs = (const float4*)(x + (size_t)s * C);
    float* ao = agg + (size_t)t * C;
#pragma unroll
    for (int i = 0; i < C / 128; i++) {
        int q = lane + i * 32;
        float4 v = xs[q];
        int c = q * 4;
        atomicAdd(ao + c + 0, v.x);
        atomicAdd(ao + c + 1, v.y);
        atomicAdd(ao + c + 2, v.z);
        atomicAdd(ao + c + 3, v.w);
    }
}

// W[K,N] fp32 -> WT fp16 [N,K]; optionally zero the BN stat accumulators
__global__ void conv_wT(const float* __restrict__ W, __half* __restrict__ hiT,
                        int K, int N, float* __restrict__ zsum, float* __restrict__ zsumsq) {
    int i = blockIdx.x * blockDim.x + threadIdx.x;
    if (zsum && blockIdx.x == 0 && threadIdx.x < HID) {
        zsum[threadIdx.x] = 0.f;
        zsumsq[threadIdx.x] = 0.f;
    }
    if (i >= K * N) return;
    int k = i / N, n = i % N;
    hiT[(size_t)n * K + k] = __float2half_rn(W[i]);
}

// compute scale/shift from stats, then re-zero stats for the next layer
__global__ void bn_prep(float* __restrict__ sum, float* __restrict__ sumsq,
                        const float* __restrict__ g, const float* __restrict__ be,
                        int M, float* __restrict__ scale, float* __restrict__ shift) {
    int c = threadIdx.x;
    float inv = 1.f / (float)M;
    float mu = sum[c] * inv;
    float var = sumsq[c] * inv - mu * mu;
    float sc = g[c] * rsqrtf(var + BN_EPS);
    scale[c] = sc;
    shift[c] = be[c] - mu * sc;
    sum[c] = 0.f;
    sumsq[c] = 0.f;
}

// ---------------- fused mma.sync GEMM, fp32 A input, pure fp16 compute ----------------
// C[M, bcol:bcol+128] = op(A)[M,KT] @ W[KT, bcol:bcol+128] + bias
//   op(A) = optional BN+ReLU per K-col. Optional output ReLU + column stats.
// A and B rounded to fp16 (rel err ~1e-4 end-to-end, measured headroom 7x).
// Tile 128x128x32, 256 threads (8 warps), grid = (M/128, 2), 2 CTAs/SM.
// A loaded to regs (LDG, 1-iter prefetch), converted in-reg, stored to smem.
// A16 x2 bufs, B x3 stages, 1 barrier/iter. smem = 53248 B.
#define BK 32
#define SPAD 40                          // tile row stride (halfs)
#define A16B (128 * SPAD * 2)            // 10240 B per A16 tile buf
#define BTB  (128 * SPAD * 2)            // 10240 B per B tile per stage
#define S_AH 0                           // 2 bufs: 20480
#define S_BH (S_AH + 2 * A16B)           // 20480 (3 stages: 30720)
#define S_SS (S_BH + 3 * BTB)            // 51200
#define GEMM_SMEM (S_SS + 2048)          // 53248

template<int KT, bool BNA, bool RELUOUT, bool STATS>
__global__ void __launch_bounds__(256, 2) gemm_f32a(
    const float* __restrict__ A, const __half* __restrict__ Bhi,
    const float* __restrict__ scale, const float* __restrict__ shift,
    const float* __restrict__ bias, float* __restrict__ C,
    float* __restrict__ gsum, float* __restrict__ gsumsq)
{
    extern __shared__ char smem[];
    const uint32_t sb = smem_u32(smem);
    const int tid = threadIdx.x, wid = tid >> 5, lane = tid & 31;
    const int wrow = wid & 3, wcol = wid >> 2;     // 4 row-warps x 2 col-warps
    constexpr int NC = KT / BK;

    const int brow = blockIdx.x * 128;
    const int bcol = blockIdx.y * 128;

    const int lr = tid >> 1;          // 0..127  (loader row, A and B)
    const int lg = tid & 1;           // 0..1    (16-elem segment)

    float* scale_s = (float*)(smem + S_SS);
    float* shift_s = scale_s + 256;
    if (BNA && tid < 256) {
        scale_s[tid] = scale[tid];
        shift_s[tid] = shift[tid];
    }

    // B stage load (cp.async, one commit group per call)
    auto load_B = [&](int c) {
        int st = c % 3;
        uint32_t bdst = (uint32_t)(lr * SPAD + lg * 16) * 2;
        const __half* pb = Bhi + (size_t)(bcol + lr) * KT + c * BK + lg * 16;
        uint32_t bh = sb + S_BH + st * BTB + bdst;
        CPA16(bh, pb); CPA16(bh + 16, pb + 8);
        CPA_COMMIT();
    };

    // A register prefetch: 16 floats per thread
    float v[16];
    auto load_A = [&](int c) {
        const float* pa = A + (size_t)(brow + lr) * KT + c * BK + lg * 16;
#pragma unroll
        for (int i = 0; i < 4; i++) {
            float4 t = *(const float4*)(pa + i * 4);
            v[i * 4 + 0] = t.x; v[i * 4 + 1] = t.y; v[i * 4 + 2] = t.z; v[i * 4 + 3] = t.w;
        }
    };

    // convert regs -> fp16 A tile (c&1); BNA reads scale_s (barrier-protected)
    auto convert = [&](int c) {
        float w[16];
#pragma unroll
        for (int i = 0; i < 16; i++) w[i] = v[i];
        if (BNA) {
            int k0 = c * BK + lg * 16;
#pragma unroll
            for (int j = 0; j < 16; j++)
                w[j] = fmaxf(fmaf(w[j], scale_s[k0 + j], shift_s[k0 + j]), 0.f);
        }
        uint32_t h[8];
#pragma unroll
        for (int i = 0; i < 8; i++) {
            __half2 p = __floats2half2_rn(w[2 * i], w[2 * i + 1]);
            h[i] = *reinterpret_cast<uint32_t*>(&p);
        }
        int ab = c & 1;
        char* dh = smem + S_AH + ab * A16B + (size_t)(lr * SPAD + lg * 16) * 2;
        *(uint4*)dh = *(uint4*)&h[0];
        *(uint4*)(dh + 16) = *(uint4*)&h[4];
    };

    float acc[2][8][4];
#pragma unroll
    for (int i = 0; i < 2; i++)
#pragma unroll
        for (int j = 0; j < 8; j++)
#pragma unroll
            for (int k = 0; k < 4; k++) acc[i][j][k] = 0.f;

    const uint32_t a_row = wrow * 32 + (lane & 15);
    const uint32_t a_coloff = (lane >> 4) * 8;
    const uint32_t b_row_l = (lane & 7) + ((lane >> 4) << 3);
    const uint32_t b_coloff = ((lane >> 3) & 1) * 8;

    // prologue: B(0), B(1) in flight; A(0) -> regs -> A16 buf0
    load_A(0);
    load_B(0);
    if (NC > 1) { load_B(1); CPA_WAIT1(); } else { CPA_WAIT0(); }
    if (BNA) __syncthreads();     // scale_s/shift_s visible before convert(0)
    convert(0);

#pragma unroll 1
    for (int c = 0; c < NC; c++) {
        // barrier: A16[c&1] converts visible; B[c%3] landed in all threads
        // (each waited its own groups <= c before arriving); mma(c-1) done.
        __syncthreads();
        if (c + 2 < NC) load_B(c + 2);
        if (c + 1 < NC) load_A(c + 1);

        const uint32_t aHiB = sb + S_AH + (c & 1) * A16B;
        const uint32_t bHiB = sb + S_BH + (c % 3) * BTB;

#pragma unroll
        for (int ks = 0; ks < 2; ks++) {
            uint32_t ao = (uint32_t)(a_row * SPAD + ks * 16 + a_coloff) * 2;
            uint32_t ah[2][4];
            ldm_x4(ah[0], aHiB + ao);
            ldm_x4(ah[1], aHiB + ao + 16 * SPAD * 2);

#pragma unroll
            for (int nt = 0; nt < 4; nt++) {
                uint32_t bo = (uint32_t)((wcol * 64 + nt * 16 + b_row_l) * SPAD + ks * 16 + b_coloff) * 2;
                uint32_t bh[4];
                ldm_x4(bh, bHiB + bo);
#pragma unroll
                for (int mf = 0; mf < 2; mf++) {
                    mma16816(acc[mf][nt * 2 + 0], ah[mf], &bh[0]);
                    mma16816(acc[mf][nt * 2 + 1], ah[mf], &bh[2]);
                }
            }
        }

        // pipeline next conversion (A regs loaded this iter; LDG latency hidden by mma)
        if (c + 1 < NC) {
            if (c + 2 < NC) CPA_WAIT1(); else CPA_WAIT0();   // B(c+1) landed (own stores)
            convert(c + 1);
        }
    }

    // ---------------- epilogue ----------------
    const int row0 = brow + wrow * 32 + (lane >> 2);
    const int col0 = wcol * 64 + (lane & 3) * 2;

    float cs[16], cq[16];
    if (STATS) {
#pragma unroll
        for (int i = 0; i < 16; i++) { cs[i] = 0.f; cq[i] = 0.f; }
    }

#pragma unroll
    for (int mf = 0; mf < 2; mf++) {
#pragma unroll
        for (int nt = 0; nt < 8; nt++) {
            float* d = acc[mf][nt];
            int col = col0 + nt * 8;
            float2 bv = *(const float2*)(bias + bcol + col);
            int r0 = row0 + mf * 16;
            float2 v0 = {d[0] + bv.x, d[1] + bv.y};
            float2 v1 = {d[2] + bv.x, d[3] + bv.y};
            if (RELUOUT) {
                v0.x = fmaxf(v0.x, 0.f); v0.y = fmaxf(v0.y, 0.f);
                v1.x = fmaxf(v1.x, 0.f); v1.y = fmaxf(v1.y, 0.f);
            }
            if (STATS) {
                int i0 = nt * 2;
                cs[i0] += v0.x + v1.x;       cq[i0] += v0.x * v0.x + v1.x * v1.x;
                cs[i0 + 1] += v0.y + v1.y;   cq[i0 + 1] += v0.y * v0.y + v1.y * v1.y;
            }
            *(float2*)(C + (size_t)r0 * HID + bcol + col) = v0;
            *(float2*)(C + (size_t)(r0 + 8) * HID + bcol + col) = v1;
        }
    }

    if (STATS) {
        // reduce over the 8 lanes sharing the same columns
#pragma unroll
        for (int off = 4; off <= 16; off <<= 1) {
#pragma unroll
            for (int i = 0; i < 16; i++) {
                cs[i] += __shfl_xor_sync(0xffffffff, cs[i], off);
                cq[i] += __shfl_xor_sync(0xffffffff, cq[i], off);
            }
        }
        __syncthreads();                       // mainloop smem no longer needed
        float* ssum = (float*)smem;            // [0..127] sum, [128..255] sumsq
        ssum[tid] = 0.f;
        __syncthreads();
        if (lane < 4) {
#pragma unroll
            for (int nt = 0; nt < 8; nt++) {
#pragma unroll
                for (int j = 0; j < 2; j++) {
                    int cl = wcol * 64 + nt * 8 + lane * 2 + j;
                    atomicAdd(&ssum[cl], cs[nt * 2 + j]);
                    atomicAdd(&ssum[128 + cl], cq[nt * 2 + j]);
                }
            }
        }
        __syncthreads();
        if (tid < 128) {
            atomicAdd(gsum + bcol + tid, ssum[tid]);
            atomicAdd(gsumsq + bcol + tid, ssum[128 + tid]);
        }
    }
}

// ---------------- small fp32 GEMM for lin2 (N=47) ----------------
template<bool RELU>
__global__ void gemm_bias(const float* __restrict__ A, const float* __restrict__ B,
                          const float* __restrict__ bias, float* __restrict__ C,
                          int M, int N, int K) {
    __shared__ float As[16][64];
    __shared__ float Bs[16][64 + 4];
    int tid = threadIdx.x;
    int tx = tid & 15, ty = tid >> 4;
    int bm = blockIdx.x * 64, bn = blockIdx.y * 64;
    float acc[4][4];
#pragma unroll
    for (int i = 0; i < 4; i++)
#pragma unroll
        for (int j = 0; j < 4; j++) acc[i][j] = 0.f;
    for (int kt = 0; kt < K; kt += 16) {
#pragma unroll
        for (int l = 0; l < 4; l++) {
            int idx = tid + l * 256;
            int m = idx >> 4, k = idx & 15;
            int row = bm + m;
            As[k][m] = (row < M) ? A[(size_t)row * K + kt + k] : 0.f;
        }
#pragma unroll
        for (int l = 0; l < 4; l++) {
            int idx = tid + l * 256;
            int k = idx >> 6, n = idx & 63;
            int col = bn + n;
            Bs[k][n] = (col < N) ? B[(size_t)(kt + k) * N + col] : 0.f;
        }
        __syncthreads();
#pragma unroll
        for (int k = 0; k < 16; k++) {
            float a[4], b[4];
#pragma unroll
            for (int i = 0; i < 4; i++) a[i] = As[k][ty * 4 + i];
#pragma unroll
            for (int j = 0; j < 4; j++) b[j] = Bs[k][tx * 4 + j];
#pragma unroll
            for (int i = 0; i < 4; i++)
#pragma unroll
                for (int j = 0; j < 4; j++) acc[i][j] += a[i] * b[j];
        }
        __syncthreads();
    }
#pragma unroll
    for (int i = 0; i < 4; i++) {
        int row = bm + ty * 4 + i;
        if (row >= M) continue;
#pragma unroll
        for (int j = 0; j < 4; j++) {
            int col = bn + tx * 4 + j;
            if (col >= N) continue;
            float v = acc[i][j] + bias[col];
            if (RELU) v = fmaxf(v, 0.f);
            C[(size_t)row * N + col] = v;
        }
    }
}

__global__ void log_softmax47(const float* __restrict__ z, float* __restrict__ out) {
    int r = blockIdx.x;
    int lane = threadIdx.x;
    const float* zr = z + (size_t)r * OUTC;
    float v0 = (lane < OUTC) ? zr[lane] : -INFINITY;
    float v1 = (lane + 32 < OUTC) ? zr[lane + 32] : -INFINITY;
    float m = fmaxf(v0, v1);
#pragma unroll
    for (int o = 16; o > 0; o >>= 1) m = fmaxf(m, __shfl_xor_sync(0xffffffff, m, o));
    float e = ((lane < OUTC) ? expf(v0 - m) : 0.f) + ((lane + 32 < OUTC) ? expf(v1 - m) : 0.f);
#pragma unroll
    for (int o = 16; o > 0; o >>= 1) e += __shfl_xor_sync(0xffffffff, e, o);
    float lse = logf(e) + m;
    if (lane < OUTC) out[(size_t)r * OUTC + lane] = v0 - lse;
    if (lane + 32 < OUTC) out[(size_t)r * OUTC + lane + 32] = v1 - lse;
}

// ---------------- host driver ----------------
extern "C" void kernel_launch(void* const* d_in, const int* in_sizes, int n_in,
                              void* d_out, int out_size) {
    const float* x = (const float*)d_in[0];
    const int* eis[3] = {(const int*)d_in[1], (const int*)d_in[2], (const int*)d_in[3]};
    const float* cw[3][6];
    for (int l = 0; l < 3; l++)
        for (int i = 0; i < 6; i++)
            cw[l][i] = (const float*)d_in[4 + l * 6 + i];
    const float* lin1_w = (const float*)d_in[22];
    const float* lin1_b = (const float*)d_in[23];
    const float* lin2_w = (const float*)d_in[24];
    const float* lin2_b = (const float*)d_in[25];
    float* out = (float*)d_out;

    float *bufA, *bufB, *sum, *sumsq, *scale, *shift;
    __half *wHi;
    cudaGetSymbolAddress((void**)&bufA, g_bufA);
    cudaGetSymbolAddress((void**)&bufB, g_bufB);
    cudaGetSymbolAddress((void**)&wHi, g_wHi);
    cudaGetSymbolAddress((void**)&sum, g_sum);
    cudaGetSymbolAddress((void**)&sumsq, g_sumsq);
    cudaGetSymbolAddress((void**)&scale, g_scale);
    cudaGetSymbolAddress((void**)&shift, g_shift);

    cudaFuncSetAttribute(gemm_f32a<128, false, false, true>,  cudaFuncAttributeMaxDynamicSharedMemorySize, GEMM_SMEM);
    cudaFuncSetAttribute(gemm_f32a<256, false, false, true>,  cudaFuncAttributeMaxDynamicSharedMemorySize, GEMM_SMEM);
    cudaFuncSetAttribute(gemm_f32a<256, true,  true,  false>, cudaFuncAttributeMaxDynamicSharedMemorySize, GEMM_SMEM);
    cudaFuncSetAttribute(gemm_f32a<256, false, true,  false>, cudaFuncAttributeMaxDynamicSharedMemorySize, GEMM_SMEM);

    const int nt[3] = {N0T, N1T, N2T};
    const int ne[3] = {E0, E1, E2};

    const float* cur = x;
    for (int l = 0; l < 3; l++) {
        int M = nt[l];
        int C = (l == 0) ? C_IN : HID;
        // buffer schedule keeps src/dst disjoint per kernel
        float* Agg = (l == 1) ? bufB : bufA;
        float* H1  = (l == 1) ? bufA : bufB;
        float* H2  = (l == 1) ? bufB : bufA;

        // launch order L0: copy(0), scatter(1), conv_wT+zero(2), gemm1(3) <- profiled
        int n4 = M * C / 4;
        copy_f4<<<min((n4 + 255) / 256, 4096), 256>>>(cur, Agg, n4);
        if (C == 128)
            agg_scatter<128><<<(ne[l] + 7) / 8, 256>>>(cur, eis[l], eis[l] + ne[l], Agg, ne[l]);
        else
            agg_scatter<256><<<(ne[l] + 7) / 8, 256>>>(cur, eis[l], eis[l] + ne[l], Agg, ne[l]);

        conv_wT<<<(C * HID + 255) / 256, 256>>>(cw[l][0], wHi + l * 65536, C, HID,
                                                (l == 0) ? sum : nullptr, (l == 0) ? sumsq : nullptr);

        // H1 = Agg @ w1 + b1, with fused column stats
        if (C == 128)
            gemm_f32a<128, false, false, true><<<dim3(M / 128, 2), 256, GEMM_SMEM>>>(
                Agg, wHi + l * 65536, nullptr, nullptr, cw[l][1], H1, sum, sumsq);
        else
            gemm_f32a<256, false, false, true><<<dim3(M / 128, 2), 256, GEMM_SMEM>>>(
                Agg, wHi + l * 65536, nullptr, nullptr, cw[l][1], H1, sum, sumsq);

        bn_prep<<<1, HID>>>(sum, sumsq, cw[l][2], cw[l][3], M, scale, shift);
        conv_wT<<<(HID * HID + 255) / 256, 256>>>(cw[l][4], wHi + (3 + l) * 65536, HID, HID, nullptr, nullptr);

        // H2 = relu( relu(BN(H1)) @ w2 + b2 ), BN+ReLU fused at A-load
        gemm_f32a<256, true, true, false><<<dim3(M / 128, 2), 256, GEMM_SMEM>>>(
            H1, wHi + (3 + l) * 65536, scale, shift, cw[l][5], H2, nullptr, nullptr);
        cur = H2;
    }

    // head: relu(cur @ lin1 + b) -> bufB ; lin2 -> bufA
    conv_wT<<<(HID * HID + 255) / 256, 256>>>(lin1_w, wHi + 6 * 65536, HID, HID, nullptr, nullptr);
    gemm_f32a<256, false, true, false><<<dim3(N2T / 128, 2), 256, GEMM_SMEM>>>(
        cur, wHi + 6 * 65536, nullptr, nullptr, lin1_b, bufB, nullptr, nullptr);
    gemm_bias<false><<<dim3((N2T + 63) / 64, 1), 256>>>(bufB, lin2_w, lin2_b, bufA, N2T, OUTC, HID);
    log_softmax47<<<N2T, 32>>>(bufA, out);
}